// round 13
// baseline (speedup 1.0000x reference)
#include <cuda_runtime.h>
#include <cuda_bf16.h>
#include <math.h>
#include <stdint.h>

#define Bb   16
#define Cc   256
#define NN   9216      // H*W
#define GG   8
#define MDm  64
#define NHh  4
#define HDd  16
#define MKQV 192
#define NBLK 144       // NN/64 column blocks

// ---------------- scratch (device globals: no allocs allowed) ----------------
__device__ float g_chansum[Bb*Cc];
__device__ float g_chansq [Bb*Cc];
__device__ __nv_bfloat16 g_xh[(size_t)Bb*Cc*NN];   // x in bf16
__device__ __nv_bfloat16 g_Wh[(size_t)Bb*MKQV*Cc];
__device__ __nv_bfloat16 g_WOh[Cc*MDm];
__device__ float g_pbias  [Bb*MKQV];
__device__ float g_gate   [Bb];
__device__ __nv_bfloat16 g_qh[(size_t)Bb*MDm*NN]; // phi_q in bf16
__device__ float g_Mpart  [(size_t)Bb*NBLK*1024];
__device__ float g_Zpart  [(size_t)Bb*NBLK*64];
__device__ float g_M      [Bb*NHh*HDd*HDd];
__device__ float g_Z      [Bb*NHh*HDd];

// ---------------- PTX helpers (baseline ISA: ldmatrix/mma.sync/cp.async) -----
__device__ __forceinline__ uint32_t smem_u32(const void* p) {
    uint32_t a;
    asm("{ .reg .u64 t; cvta.to.shared.u64 t, %1; cvt.u32.u64 %0, t; }" : "=r"(a) : "l"(p));
    return a;
}
__device__ __forceinline__ void ldsm4(uint32_t* r, uint32_t addr) {
    asm volatile("ldmatrix.sync.aligned.m8n8.x4.shared.b16 {%0,%1,%2,%3}, [%4];"
        : "=r"(r[0]), "=r"(r[1]), "=r"(r[2]), "=r"(r[3]) : "r"(addr));
}
__device__ __forceinline__ void ldsm4t(uint32_t* r, uint32_t addr) {
    asm volatile("ldmatrix.sync.aligned.m8n8.x4.trans.shared.b16 {%0,%1,%2,%3}, [%4];"
        : "=r"(r[0]), "=r"(r[1]), "=r"(r[2]), "=r"(r[3]) : "r"(addr));
}
__device__ __forceinline__ void mma16816(float* d, const uint32_t* a, const uint32_t* b) {
    asm volatile("mma.sync.aligned.m16n8k16.row.col.f32.bf16.bf16.f32 "
        "{%0,%1,%2,%3}, {%4,%5,%6,%7}, {%8,%9}, {%0,%1,%2,%3};"
        : "+f"(d[0]), "+f"(d[1]), "+f"(d[2]), "+f"(d[3])
        : "r"(a[0]), "r"(a[1]), "r"(a[2]), "r"(a[3]), "r"(b[0]), "r"(b[1]));
}
__device__ __forceinline__ void cp16(uint32_t dst, const void* src) {
    asm volatile("cp.async.cg.shared.global [%0], [%1], 16;" :: "r"(dst), "l"(src));
}
#define CP_COMMIT() asm volatile("cp.async.commit_group;" ::: "memory")
#define CP_WAIT0()  asm volatile("cp.async.wait_group 0;" ::: "memory")

// ---------------- K0: per-(b,c) sum/sumsq + bf16 cast of x -------------------
__global__ void __launch_bounds__(256) k_stats(const float* __restrict__ x) {
    int bc = blockIdx.x;
    int t  = threadIdx.x;
    const float4* p = (const float4*)(x + (size_t)bc * NN);
    __nv_bfloat16* xh = g_xh + (size_t)bc * NN;
    float s = 0.f, sq = 0.f;
    #pragma unroll
    for (int i = 0; i < NN/1024; i++) {
        float4 v = p[t + i*256];
        s += (v.x + v.y) + (v.z + v.w);
        sq = fmaf(v.x, v.x, sq);
        sq = fmaf(v.y, v.y, sq);
        sq = fmaf(v.z, v.z, sq);
        sq = fmaf(v.w, v.w, sq);
        __nv_bfloat162 h01 = __float22bfloat162_rn(make_float2(v.x, v.y));
        __nv_bfloat162 h23 = __float22bfloat162_rn(make_float2(v.z, v.w));
        int e = (t + i*256) * 4;
        uint2 uh;
        uh.x = *(uint32_t*)&h01; uh.y = *(uint32_t*)&h23;
        *(uint2*)&xh[e] = uh;
    }
    #pragma unroll
    for (int o = 16; o; o >>= 1) {
        s  += __shfl_down_sync(0xffffffffu, s,  o);
        sq += __shfl_down_sync(0xffffffffu, sq, o);
    }
    __shared__ float ss[8], sqs[8];
    if ((t & 31) == 0) { ss[t>>5] = s; sqs[t>>5] = sq; }
    __syncthreads();
    if (t == 0) {
        float a = 0.f, b2 = 0.f;
        #pragma unroll
        for (int w = 0; w < 8; w++) { a += ss[w]; b2 += sqs[w]; }
        g_chansum[bc] = a;
        g_chansq [bc] = b2;
    }
}

// ---------------- K1: group stats, weight fold+bf16, Wout bf16, gate MLP -----
__global__ void __launch_bounds__(256) k_prep(
    const float* __restrict__ norm_w, const float* __restrict__ norm_b,
    const float* __restrict__ Wk, const float* __restrict__ Wv, const float* __restrict__ Wq,
    const float* __restrict__ Wout,
    const float* __restrict__ Wg1, const float* __restrict__ bg1,
    const float* __restrict__ Wg2, const float* __restrict__ bg2,
    float* __restrict__ out, int has_tail, long long tail_off)
{
    int b = blockIdx.x;
    int t = threadIdx.x;
    __shared__ float mu_s[GG], rs_s[GG];
    __shared__ float alpha_s[Cc], beta_s[Cc], pooled[Cc];
    __shared__ float g1v[MDm];

    if (b == 0) {
        #pragma unroll
        for (int j = 0; j < MDm; j++)
            g_WOh[t*MDm + j] = __float2bfloat16_rn(Wout[t*MDm + j]);
    }

    if (t < GG) {
        float s = 0.f, sq = 0.f;
        for (int c = 0; c < 32; c++) {
            s  += g_chansum[b*Cc + t*32 + c];
            sq += g_chansq [b*Cc + t*32 + c];
        }
        float inv = 1.0f / (32.0f * (float)NN);
        float mu  = s * inv;
        float var = sq * inv - mu * mu;
        mu_s[t] = mu;
        rs_s[t] = rsqrtf(var + 1e-5f);
    }
    __syncthreads();
    {
        int c = t, g = c >> 5;
        float a  = rs_s[g] * norm_w[c];
        float be = norm_b[c] - mu_s[g] * a;
        alpha_s[c] = a;
        beta_s [c] = be;
        pooled [c] = g_chansum[b*Cc + c] * (1.0f/(float)NN) * a + be;
    }
    __syncthreads();
    for (int m = 0; m < MKQV; m++) {
        const float* Wsrc = (m < 64) ? (Wk + m*Cc)
                          : (m < 128) ? (Wv + (m-64)*Cc)
                                      : (Wq + (m-128)*Cc);
        g_Wh[(size_t)b*MKQV*Cc + m*Cc + t] = __float2bfloat16_rn(Wsrc[t] * alpha_s[t]);
    }
    if (t < MKQV) {
        const float* Wsrc = (t < 64) ? (Wk + t*Cc)
                          : (t < 128) ? (Wv + (t-64)*Cc)
                                      : (Wq + (t-128)*Cc);
        float s = 0.f;
        for (int c = 0; c < Cc; c++) s = fmaf(Wsrc[c], beta_s[c], s);
        g_pbias[b*MKQV + t] = s;
    }
    __syncthreads();
    if (t < MDm) {
        float h = bg1[t];
        for (int c = 0; c < Cc; c++) h = fmaf(Wg1[t*Cc + c], pooled[c], h);
        g1v[t] = 0.5f * h * (1.0f + erff(h * 0.70710678118654752f));
    }
    __syncthreads();
    if (t == 0) {
        float s = bg2[0];
        #pragma unroll
        for (int j = 0; j < MDm; j++) s = fmaf(Wg2[j], g1v[j], s);
        float gv = 1.0f / (1.0f + expf(-s));
        g_gate[b] = gv;
        if (has_tail) out[tail_off + b] = gv;
    }
}

// ---------------- K2: 1-term bf16 HMMA KQV GEMM, cp.async dbl-buffered -------
// per-buffer: A 27648 | BH 9216 = 36864
#define P_A     0
#define P_BH    27648
#define PBUF    36864
#define S_TOTAL 73728
// epilogue union:
#define S_KV    0                         // float[128][68]  34816
#define S_QS    36864                     // float[64][68]   17408

__global__ void __launch_bounds__(256,3) k_proj() {
    extern __shared__ char smem[];
    uint32_t sb = smem_u32(smem);
    int b   = blockIdx.y;
    int nb  = blockIdx.x;
    int n0  = nb * 64;
    int tid = threadIdx.x;
    int wid = tid >> 5, lane = tid & 31;
    int warp_m = wid >> 1;
    int warp_n = wid & 1;

    const __nv_bfloat16* wh = g_Wh + (size_t)b*MKQV*Cc;
    const __nv_bfloat16* xh = g_xh + (size_t)b*Cc*NN + n0;

    float acc[3][4][4];
    #pragma unroll
    for (int i = 0; i < 3; i++)
        #pragma unroll
        for (int j = 0; j < 4; j++)
            #pragma unroll
            for (int r = 0; r < 4; r++) acc[i][j][r] = 0.f;

    uint32_t aRowOff  = (uint32_t)(warp_m*48 + (lane & 15)) * 144 + (lane >> 4) * 16;
    uint32_t bRowOff  = (uint32_t)(lane & 15) * 144
                      + (uint32_t)(warp_n*32 + (lane >> 4) * 8) * 2;

    // prologue: chunk 0 -> buffer 0
    {
        #pragma unroll
        for (int i = 0; i < 6; i++) {
            int l = tid + i*256;
            int m = l >> 3, j = l & 7;
            cp16(sb + P_A + m*144 + j*16, wh + (size_t)m*Cc + j*8);
        }
        #pragma unroll
        for (int i = 0; i < 2; i++) {
            int l = tid + i*256;
            int k = l >> 3, j = l & 7;
            cp16(sb + P_BH + k*144 + j*16, xh + (size_t)k*NN + j*8);
        }
        CP_COMMIT();
    }

    for (int c = 0; c < 4; c++) {
        uint32_t buf = (uint32_t)(c & 1) * PBUF;
        CP_WAIT0();
        __syncthreads();
        if (c < 3) {
            int kk = (c + 1) * 64;
            uint32_t nbuf = buf ^ PBUF;
            #pragma unroll
            for (int i = 0; i < 6; i++) {
                int l = tid + i*256;
                int m = l >> 3, j = l & 7;
                cp16(sb + nbuf + P_A + m*144 + j*16, wh + (size_t)m*Cc + kk + j*8);
            }
            #pragma unroll
            for (int i = 0; i < 2; i++) {
                int l = tid + i*256;
                int k = l >> 3, j = l & 7;
                cp16(sb + nbuf + P_BH + k*144 + j*16, xh + (size_t)(kk + k)*NN + j*8);
            }
            CP_COMMIT();
        }
        #pragma unroll
        for (int ks = 0; ks < 4; ks++) {
            uint32_t kByte = (uint32_t)(ks * 16) * 2;
            uint32_t ah[3][4], bh[2][4];
            #pragma unroll
            for (int fm = 0; fm < 3; fm++)
                ldsm4(ah[fm], sb + buf + P_A + aRowOff + (uint32_t)fm*16*144 + kByte);
            #pragma unroll
            for (int p = 0; p < 2; p++)
                ldsm4t(bh[p], sb + buf + P_BH + bRowOff + (uint32_t)(ks*16)*144 + (uint32_t)p*16*2);
            #pragma unroll
            for (int fm = 0; fm < 3; fm++) {
                #pragma unroll
                for (int p = 0; p < 2; p++) {
                    mma16816(acc[fm][p*2+0], ah[fm], &bh[p][0]);
                    mma16816(acc[fm][p*2+1], ah[fm], &bh[p][2]);
                }
            }
        }
    }
    __syncthreads();

    float (*KV)[68] = (float(*)[68])(smem + S_KV);
    float (*QS)[68] = (float(*)[68])(smem + S_QS);

    #pragma unroll
    for (int fm = 0; fm < 3; fm++) {
        #pragma unroll
        for (int fn = 0; fn < 4; fn++) {
            float* d = acc[fm][fn];
            int n = warp_n*32 + fn*8 + (lane & 3)*2;
            #pragma unroll
            for (int rh = 0; rh < 2; rh++) {
                int m = warp_m*48 + fm*16 + (lane >> 2) + rh*8;
                float pb = g_pbias[b*MKQV + m];
                float v0 = d[rh*2+0] + pb, v1 = d[rh*2+1] + pb;
                if (m < 64 || m >= 128) {
                    v0 = (v0 > 0.f) ? (v0 + 1.f) : expf(v0);
                    v1 = (v1 > 0.f) ? (v1 + 1.f) : expf(v1);
                }
                float2 o = make_float2(v0, v1);
                if (m < 128) *(float2*)&KV[m][n]      = o;
                else         *(float2*)&QS[m-128][n]  = o;
            }
        }
    }
    __syncthreads();

    {   // q writeout as bf16 (coalesced: 16 bf16 = 32B per thread)
        int r2 = tid >> 2, qt = tid & 3;
        __nv_bfloat16* dst = g_qh + ((size_t)b*MDm + r2)*NN + n0 + qt*16;
        uint32_t pk[8];
        #pragma unroll
        for (int j = 0; j < 8; j++) {
            float2 v = *(const float2*)&QS[r2][qt*16 + j*2];
            __nv_bfloat162 h = __float22bfloat162_rn(v);
            pk[j] = *(uint32_t*)&h;
        }
        *(uint4*)(dst)     = *(uint4*)&pk[0];
        *(uint4*)(dst + 8) = *(uint4*)&pk[4];
    }
    {
        int h = tid >> 6, d = (tid >> 2) & 15, e0 = (tid & 3) * 4;
        float m0 = 0.f, m1 = 0.f, m2 = 0.f, m3 = 0.f;
        #pragma unroll
        for (int n = 0; n < 64; n += 4) {
            float4 a  = *(const float4*)&KV[h*16 + d][n];
            float4 b0 = *(const float4*)&KV[64 + h*16 + e0 + 0][n];
            float4 b1 = *(const float4*)&KV[64 + h*16 + e0 + 1][n];
            float4 b2 = *(const float4*)&KV[64 + h*16 + e0 + 2][n];
            float4 b3 = *(const float4*)&KV[64 + h*16 + e0 + 3][n];
            m0 = fmaf(a.x,b0.x, fmaf(a.y,b0.y, fmaf(a.z,b0.z, fmaf(a.w,b0.w, m0))));
            m1 = fmaf(a.x,b1.x, fmaf(a.y,b1.y, fmaf(a.z,b1.z, fmaf(a.w,b1.w, m1))));
            m2 = fmaf(a.x,b2.x, fmaf(a.y,b2.y, fmaf(a.z,b2.z, fmaf(a.w,b2.w, m2))));
            m3 = fmaf(a.x,b3.x, fmaf(a.y,b3.y, fmaf(a.z,b3.z, fmaf(a.w,b3.w, m3))));
        }
        *(float4*)&g_Mpart[((size_t)(b*NBLK + nb))*1024 + tid*4] = make_float4(m0,m1,m2,m3);
    }
    if (tid < 64) {
        float z = 0.f;
        #pragma unroll
        for (int n = 0; n < 64; n += 4) {
            float4 a = *(const float4*)&KV[tid][n];
            z += (a.x + a.y) + (a.z + a.w);
        }
        g_Zpart[((size_t)(b*NBLK + nb))*64 + tid] = z;
    }
}

// ---------------- K3: reduce partials -> M, Z (4-way split chains) ----------
__global__ void __launch_bounds__(256) k_red(const float* __restrict__ M0,
                                             const float* __restrict__ Z0) {
    int b = blockIdx.y, chunk = blockIdx.x;
    int t = threadIdx.x;
    int li = t & 63, grp = t >> 6;
    int idx = chunk*64 + li;
    __shared__ float red[4][64];
    __shared__ float zred[4][64];

    float acc = 0.f;
    const float* base = g_Mpart + (size_t)b*NBLK*1024 + idx;
    #pragma unroll 4
    for (int nb = grp; nb < NBLK; nb += 4) acc += base[(size_t)nb*1024];
    red[grp][li] = acc;

    float zacc = 0.f;
    if (chunk == 0) {
        const float* zb = g_Zpart + (size_t)b*NBLK*64 + li;
        #pragma unroll 4
        for (int nb = grp; nb < NBLK; nb += 4) zacc += zb[(size_t)nb*64];
        zred[grp][li] = zacc;
    }
    __syncthreads();
    if (grp == 0) {
        float s = red[0][li] + red[1][li] + red[2][li] + red[3][li];
        g_M[b*1024 + idx] = s + M0[idx];
        if (chunk == 0) {
            float z = zred[0][li] + zred[1][li] + zred[2][li] + zred[3][li];
            g_Z[b*64 + li] = z + Z0[li];
        }
    }
}

// ---------------- K4: retrieval + 1-term bf16 HMMA Wout GEMM -----------------
#define O_Q    0                          // float q[64][68]      17408 (reused as ybuf)
#define O_MS   17408                      // float Ms[4][16][16]   4096
#define O_ZS   21504                      // float Zs[64]           256
#define O_RD   21760                      // float rd[4][64]       1024
#define O_YH   22784                      // bf16 y hi [64][72]    9216
#define O_AWH  32000                      // bf16 Wout hi [256][72] 36864
#define O_TOTAL 68864

__global__ void __launch_bounds__(256,3) k_out(const float* __restrict__ x,
                                               const float* __restrict__ bout,
                                               float* __restrict__ out) {
    extern __shared__ char smem[];
    uint32_t sb = smem_u32(smem);
    int b  = blockIdx.y;
    int n0 = blockIdx.x * 64;
    int t  = threadIdx.x;
    int lane = t & 31, wid = t >> 5;
    int warp_m = wid >> 1, warp_n = wid & 1;

    float (*q)[68]  = (float(*)[68])(smem + O_Q);
    float* Ms       = (float*)(smem + O_MS);
    float* Zs       = (float*)(smem + O_ZS);
    float (*rd)[64] = (float(*)[64])(smem + O_RD);
    __nv_bfloat16* YH  = (__nv_bfloat16*)(smem + O_YH);

    #pragma unroll
    for (int i = 0; i < 8; i++) {
        int l = t + i*256;
        int m = l >> 3, j = l & 7;
        *(uint4*)(smem + O_AWH + m*144 + j*16) = *(const uint4*)(g_WOh + m*MDm + j*8);
    }
    #pragma unroll
    for (int i = 0; i < 4; i++) {
        int idx = t + i*256;
        Ms[idx] = g_M[b*1024 + idx];
    }
    if (t < 64) Zs[t] = g_Z[b*64 + t];
    #pragma unroll
    for (int i = 0; i < 4; i++) {       // q load: bf16 -> fp32 smem
        int l = t + i*256;
        int m = l >> 4, n4 = l & 15;
        uint2 raw = *(const uint2*)(g_qh + ((size_t)b*MDm + m)*NN + n0 + n4*4);
        __nv_bfloat162 p0 = *(__nv_bfloat162*)&raw.x;
        __nv_bfloat162 p1 = *(__nv_bfloat162*)&raw.y;
        float2 f0 = __bfloat1622float2(p0);
        float2 f1 = __bfloat1622float2(p1);
        q[m][n4*4+0] = f0.x; q[m][n4*4+1] = f0.y;
        q[m][n4*4+2] = f1.x; q[m][n4*4+3] = f1.y;
    }
    __syncthreads();
    {
        int h = t >> 6, n = t & 63;
        float s = 0.f;
        #pragma unroll
        for (int d2 = 0; d2 < 16; d2++)
            s = fmaf(Zs[h*16 + d2], q[h*16 + d2][n], s);
        rd[h][n] = 1.0f / fmaxf(s, 1e-4f);
    }
    __syncthreads();
    {   // y = (M @ phi_q)/den -> bf16 in smem
        int n = t & 63, h = t >> 6;
        float qd[16];
        #pragma unroll
        for (int d2 = 0; d2 < 16; d2++) qd[d2] = q[h*16 + d2][n];
        float acc2[16];
        #pragma unroll
        for (int j = 0; j < 16; j++) acc2[j] = 0.f;
        #pragma unroll
        for (int d2 = 0; d2 < 16; d2++) {
            float qv = qd[d2];
            #pragma unroll
            for (int j = 0; j < 16; j++)
                acc2[j] = fmaf(Ms[(h*16 + d2)*16 + j], qv, acc2[j]);
        }
        float r = rd[h][n];
        #pragma unroll
        for (int j = 0; j < 16; j++)
            YH[(h*16 + j)*72 + n] = __float2bfloat16_rn(acc2[j] * r);
    }
    __syncthreads();

    // HMMA: out[256 x 64] = WoutH @ yH
    float acc[4][4][4];
    #pragma unroll
    for (int i = 0; i < 4; i++)
        #pragma unroll
        for (int j = 0; j < 4; j++)
            #pragma unroll
            for (int r = 0; r < 4; r++) acc[i][j][r] = 0.f;

    uint32_t aRowOff = (uint32_t)(warp_m*64 + (lane & 15)) * 144 + (lane >> 4) * 16;
    uint32_t bRowOff = (uint32_t)(lane & 15) * 144
                     + (uint32_t)(warp_n*32 + (lane >> 4) * 8) * 2;

    #pragma unroll
    for (int ks = 0; ks < 4; ks++) {
        uint32_t kByte = (uint32_t)(ks * 16) * 2;
        uint32_t ah[4][4], bh[2][4];
        #pragma unroll
        for (int fm = 0; fm < 4; fm++)
            ldsm4(ah[fm], sb + O_AWH + aRowOff + (uint32_t)fm*16*144 + kByte);
        #pragma unroll
        for (int p = 0; p < 2; p++)
            ldsm4t(bh[p], sb + O_YH + bRowOff + (uint32_t)(ks*16)*144 + (uint32_t)p*16*2);
        #pragma unroll
        for (int fm = 0; fm < 4; fm++) {
            #pragma unroll
            for (int p = 0; p < 2; p++) {
                mma16816(acc[fm][p*2+0], ah[fm], &bh[p][0]);
                mma16816(acc[fm][p*2+1], ah[fm], &bh[p][2]);
            }
        }
    }

    // coalesced epilogue: 4 phases of 64 rows, fragments -> smem -> float4 IO
    float gv = g_gate[b];
    float (*yb)[68] = (float(*)[68])(smem + O_Q);
    #pragma unroll
    for (int g = 0; g < 4; g++) {
        __syncthreads();
        if (warp_m == g) {
            #pragma unroll
            for (int fm = 0; fm < 4; fm++) {
                #pragma unroll
                for (int rh = 0; rh < 2; rh++) {
                    int mr = fm*16 + (lane >> 2) + rh*8;
                    float bo = bout[g*64 + mr];
                    #pragma unroll
                    for (int fn = 0; fn < 4; fn++) {
                        int n = warp_n*32 + fn*8 + (lane & 3)*2;
                        yb[mr][n]   = gv * (acc[fm][fn][rh*2+0] + bo);
                        yb[mr][n+1] = gv * (acc[fm][fn][rh*2+1] + bo);
                    }
                }
            }
        }
        __syncthreads();
        #pragma unroll
        for (int i = 0; i < 4; i++) {
            int l = t + i*256;
            int mr = l >> 4, n4 = l & 15;
            int m = g*64 + mr;
            const float* xp = x   + ((size_t)b*Cc + m)*NN + n0 + n4*4;
            float*       op = out + ((size_t)b*Cc + m)*NN + n0 + n4*4;
            float4 xv = *(const float4*)xp;
            float4 yv = *(const float4*)&yb[mr][n4*4];
            float4 r;
            r.x = xv.x + yv.x;
            r.y = xv.y + yv.y;
            r.z = xv.z + yv.z;
            r.w = xv.w + yv.w;
            *(float4*)op = r;
        }
    }
}

// ---------------- launch ----------------
extern "C" void kernel_launch(void* const* d_in, const int* in_sizes, int n_in,
                              void* d_out, int out_size) {
    const float* x      = (const float*)d_in[0];
    const float* norm_w = (const float*)d_in[1];
    const float* norm_b = (const float*)d_in[2];
    const float* Wk     = (const float*)d_in[3];
    const float* Wv     = (const float*)d_in[4];
    const float* Wq     = (const float*)d_in[5];
    const float* Wout   = (const float*)d_in[6];
    const float* bout   = (const float*)d_in[7];
    const float* M0     = (const float*)d_in[8];
    const float* Z0     = (const float*)d_in[9];
    const float* Wg1    = (const float*)d_in[10];
    const float* bg1    = (const float*)d_in[11];
    const float* Wg2    = (const float*)d_in[12];
    const float* bg2    = (const float*)d_in[13];
    float* out = (float*)d_out;

    long long mainsz = (long long)Bb * Cc * NN;
    int has_tail = ((long long)out_size >= mainsz + Bb) ? 1 : 0;

    cudaFuncSetAttribute(k_proj, cudaFuncAttributeMaxDynamicSharedMemorySize, S_TOTAL);
    cudaFuncSetAttribute(k_out,  cudaFuncAttributeMaxDynamicSharedMemorySize, O_TOTAL);

    k_stats<<<Bb*Cc, 256>>>(x);
    k_prep <<<Bb, 256>>>(norm_w, norm_b, Wk, Wv, Wq, Wout, Wg1, bg1, Wg2, bg2,
                         out, has_tail, mainsz);
    k_proj <<<dim3(NBLK, Bb), 256, S_TOTAL>>>();
    k_red  <<<dim3(16, Bb), 256>>>(M0, Z0);
    k_out  <<<dim3(NBLK, Bb), 256, O_TOTAL>>>(x, bout, out);
}

// round 14
// speedup vs baseline: 1.0852x; 1.0852x over previous
#include <cuda_runtime.h>
#include <cuda_bf16.h>
#include <math.h>
#include <stdint.h>

#define Bb   16
#define Cc   256
#define NN   9216      // H*W
#define GG   8
#define MDm  64
#define NHh  4
#define HDd  16
#define MKQV 192
#define NBLK 144       // NN/64 column blocks

// ---------------- scratch (device globals: no allocs allowed) ----------------
__device__ float g_chansum[Bb*Cc];
__device__ float g_chansq [Bb*Cc];
__device__ __nv_bfloat16 g_xh[(size_t)Bb*Cc*NN];   // x in bf16
__device__ __nv_bfloat16 g_Wh[(size_t)Bb*MKQV*Cc];
__device__ __nv_bfloat16 g_WOh[Cc*MDm];
__device__ float g_pbias  [Bb*MKQV];
__device__ float g_gate   [Bb];
__device__ __nv_bfloat16 g_qh[(size_t)Bb*MDm*NN]; // phi_q in bf16
__device__ float g_Mpart  [(size_t)Bb*NBLK*1024];
__device__ float g_Zpart  [(size_t)Bb*NBLK*64];
__device__ float g_M      [Bb*NHh*HDd*HDd];
__device__ float g_Z      [Bb*NHh*HDd];

// ---------------- PTX helpers (baseline ISA: ldmatrix/mma.sync/cp.async) -----
__device__ __forceinline__ uint32_t smem_u32(const void* p) {
    uint32_t a;
    asm("{ .reg .u64 t; cvta.to.shared.u64 t, %1; cvt.u32.u64 %0, t; }" : "=r"(a) : "l"(p));
    return a;
}
__device__ __forceinline__ void ldsm4(uint32_t* r, uint32_t addr) {
    asm volatile("ldmatrix.sync.aligned.m8n8.x4.shared.b16 {%0,%1,%2,%3}, [%4];"
        : "=r"(r[0]), "=r"(r[1]), "=r"(r[2]), "=r"(r[3]) : "r"(addr));
}
__device__ __forceinline__ void ldsm4t(uint32_t* r, uint32_t addr) {
    asm volatile("ldmatrix.sync.aligned.m8n8.x4.trans.shared.b16 {%0,%1,%2,%3}, [%4];"
        : "=r"(r[0]), "=r"(r[1]), "=r"(r[2]), "=r"(r[3]) : "r"(addr));
}
__device__ __forceinline__ void mma16816(float* d, const uint32_t* a, const uint32_t* b) {
    asm volatile("mma.sync.aligned.m16n8k16.row.col.f32.bf16.bf16.f32 "
        "{%0,%1,%2,%3}, {%4,%5,%6,%7}, {%8,%9}, {%0,%1,%2,%3};"
        : "+f"(d[0]), "+f"(d[1]), "+f"(d[2]), "+f"(d[3])
        : "r"(a[0]), "r"(a[1]), "r"(a[2]), "r"(a[3]), "r"(b[0]), "r"(b[1]));
}
__device__ __forceinline__ void cp16(uint32_t dst, const void* src) {
    asm volatile("cp.async.cg.shared.global [%0], [%1], 16;" :: "r"(dst), "l"(src));
}
#define CP_COMMIT() asm volatile("cp.async.commit_group;" ::: "memory")
#define CP_WAIT0()  asm volatile("cp.async.wait_group 0;" ::: "memory")

// ---------------- K0: per-(b,c) sum/sumsq + bf16 cast of x -------------------
__global__ void __launch_bounds__(256) k_stats(const float* __restrict__ x) {
    int bc = blockIdx.x;
    int t  = threadIdx.x;
    const float4* p = (const float4*)(x + (size_t)bc * NN);
    __nv_bfloat16* xh = g_xh + (size_t)bc * NN;
    float s = 0.f, sq = 0.f;
    #pragma unroll
    for (int i = 0; i < NN/1024; i++) {
        float4 v = p[t + i*256];
        s += (v.x + v.y) + (v.z + v.w);
        sq = fmaf(v.x, v.x, sq);
        sq = fmaf(v.y, v.y, sq);
        sq = fmaf(v.z, v.z, sq);
        sq = fmaf(v.w, v.w, sq);
        __nv_bfloat162 h01 = __float22bfloat162_rn(make_float2(v.x, v.y));
        __nv_bfloat162 h23 = __float22bfloat162_rn(make_float2(v.z, v.w));
        int e = (t + i*256) * 4;
        uint2 uh;
        uh.x = *(uint32_t*)&h01; uh.y = *(uint32_t*)&h23;
        *(uint2*)&xh[e] = uh;
    }
    #pragma unroll
    for (int o = 16; o; o >>= 1) {
        s  += __shfl_down_sync(0xffffffffu, s,  o);
        sq += __shfl_down_sync(0xffffffffu, sq, o);
    }
    __shared__ float ss[8], sqs[8];
    if ((t & 31) == 0) { ss[t>>5] = s; sqs[t>>5] = sq; }
    __syncthreads();
    if (t == 0) {
        float a = 0.f, b2 = 0.f;
        #pragma unroll
        for (int w = 0; w < 8; w++) { a += ss[w]; b2 += sqs[w]; }
        g_chansum[bc] = a;
        g_chansq [bc] = b2;
    }
}

// ---------------- K1: group stats, weight fold+bf16, Wout bf16, gate MLP -----
__global__ void __launch_bounds__(256) k_prep(
    const float* __restrict__ norm_w, const float* __restrict__ norm_b,
    const float* __restrict__ Wk, const float* __restrict__ Wv, const float* __restrict__ Wq,
    const float* __restrict__ Wout,
    const float* __restrict__ Wg1, const float* __restrict__ bg1,
    const float* __restrict__ Wg2, const float* __restrict__ bg2,
    float* __restrict__ out, int has_tail, long long tail_off)
{
    int b = blockIdx.x;
    int t = threadIdx.x;
    __shared__ float mu_s[GG], rs_s[GG];
    __shared__ float alpha_s[Cc], beta_s[Cc], pooled[Cc];
    __shared__ float g1v[MDm];

    if (b == 0) {
        #pragma unroll
        for (int j = 0; j < MDm; j++)
            g_WOh[t*MDm + j] = __float2bfloat16_rn(Wout[t*MDm + j]);
    }

    if (t < GG) {
        float s = 0.f, sq = 0.f;
        for (int c = 0; c < 32; c++) {
            s  += g_chansum[b*Cc + t*32 + c];
            sq += g_chansq [b*Cc + t*32 + c];
        }
        float inv = 1.0f / (32.0f * (float)NN);
        float mu  = s * inv;
        float var = sq * inv - mu * mu;
        mu_s[t] = mu;
        rs_s[t] = rsqrtf(var + 1e-5f);
    }
    __syncthreads();
    {
        int c = t, g = c >> 5;
        float a  = rs_s[g] * norm_w[c];
        float be = norm_b[c] - mu_s[g] * a;
        alpha_s[c] = a;
        beta_s [c] = be;
        pooled [c] = g_chansum[b*Cc + c] * (1.0f/(float)NN) * a + be;
    }
    __syncthreads();
    for (int m = 0; m < MKQV; m++) {
        const float* Wsrc = (m < 64) ? (Wk + m*Cc)
                          : (m < 128) ? (Wv + (m-64)*Cc)
                                      : (Wq + (m-128)*Cc);
        g_Wh[(size_t)b*MKQV*Cc + m*Cc + t] = __float2bfloat16_rn(Wsrc[t] * alpha_s[t]);
    }
    if (t < MKQV) {
        const float* Wsrc = (t < 64) ? (Wk + t*Cc)
                          : (t < 128) ? (Wv + (t-64)*Cc)
                                      : (Wq + (t-128)*Cc);
        float s = 0.f;
        for (int c = 0; c < Cc; c++) s = fmaf(Wsrc[c], beta_s[c], s);
        g_pbias[b*MKQV + t] = s;
    }
    __syncthreads();
    if (t < MDm) {
        float h = bg1[t];
        for (int c = 0; c < Cc; c++) h = fmaf(Wg1[t*Cc + c], pooled[c], h);
        g1v[t] = 0.5f * h * (1.0f + erff(h * 0.70710678118654752f));
    }
    __syncthreads();
    if (t == 0) {
        float s = bg2[0];
        #pragma unroll
        for (int j = 0; j < MDm; j++) s = fmaf(Wg2[j], g1v[j], s);
        float gv = 1.0f / (1.0f + expf(-s));
        g_gate[b] = gv;
        if (has_tail) out[tail_off + b] = gv;
    }
}

// ---------------- K2: 1-term bf16 HMMA KQV GEMM, cp.async dbl-buffered -------
// per-buffer: A 27648 | BH 9216 = 36864
#define P_A     0
#define P_BH    27648
#define PBUF    36864
#define S_TOTAL 73728
// epilogue union:
#define S_KV    0                         // float[128][68]  34816
#define S_QS    36864                     // float[64][68]   17408

__global__ void __launch_bounds__(256,3) k_proj() {
    extern __shared__ char smem[];
    uint32_t sb = smem_u32(smem);
    int b   = blockIdx.y;
    int nb  = blockIdx.x;
    int n0  = nb * 64;
    int tid = threadIdx.x;
    int wid = tid >> 5, lane = tid & 31;
    int warp_m = wid >> 1;
    int warp_n = wid & 1;

    const __nv_bfloat16* wh = g_Wh + (size_t)b*MKQV*Cc;
    const __nv_bfloat16* xh = g_xh + (size_t)b*Cc*NN + n0;

    float acc[3][4][4];
    #pragma unroll
    for (int i = 0; i < 3; i++)
        #pragma unroll
        for (int j = 0; j < 4; j++)
            #pragma unroll
            for (int r = 0; r < 4; r++) acc[i][j][r] = 0.f;

    uint32_t aRowOff  = (uint32_t)(warp_m*48 + (lane & 15)) * 144 + (lane >> 4) * 16;
    uint32_t bRowOff  = (uint32_t)(lane & 15) * 144
                      + (uint32_t)(warp_n*32 + (lane >> 4) * 8) * 2;

    // prologue: chunk 0 -> buffer 0
    {
        #pragma unroll
        for (int i = 0; i < 6; i++) {
            int l = tid + i*256;
            int m = l >> 3, j = l & 7;
            cp16(sb + P_A + m*144 + j*16, wh + (size_t)m*Cc + j*8);
        }
        #pragma unroll
        for (int i = 0; i < 2; i++) {
            int l = tid + i*256;
            int k = l >> 3, j = l & 7;
            cp16(sb + P_BH + k*144 + j*16, xh + (size_t)k*NN + j*8);
        }
        CP_COMMIT();
    }

    for (int c = 0; c < 4; c++) {
        uint32_t buf = (uint32_t)(c & 1) * PBUF;
        CP_WAIT0();
        __syncthreads();
        if (c < 3) {
            int kk = (c + 1) * 64;
            uint32_t nbuf = buf ^ PBUF;
            #pragma unroll
            for (int i = 0; i < 6; i++) {
                int l = tid + i*256;
                int m = l >> 3, j = l & 7;
                cp16(sb + nbuf + P_A + m*144 + j*16, wh + (size_t)m*Cc + kk + j*8);
            }
            #pragma unroll
            for (int i = 0; i < 2; i++) {
                int l = tid + i*256;
                int k = l >> 3, j = l & 7;
                cp16(sb + nbuf + P_BH + k*144 + j*16, xh + (size_t)(kk + k)*NN + j*8);
            }
            CP_COMMIT();
        }
        #pragma unroll
        for (int ks = 0; ks < 4; ks++) {
            uint32_t kByte = (uint32_t)(ks * 16) * 2;
            uint32_t ah[3][4], bh[2][4];
            #pragma unroll
            for (int fm = 0; fm < 3; fm++)
                ldsm4(ah[fm], sb + buf + P_A + aRowOff + (uint32_t)fm*16*144 + kByte);
            #pragma unroll
            for (int p = 0; p < 2; p++)
                ldsm4t(bh[p], sb + buf + P_BH + bRowOff + (uint32_t)(ks*16)*144 + (uint32_t)p*16*2);
            #pragma unroll
            for (int fm = 0; fm < 3; fm++) {
                #pragma unroll
                for (int p = 0; p < 2; p++) {
                    mma16816(acc[fm][p*2+0], ah[fm], &bh[p][0]);
                    mma16816(acc[fm][p*2+1], ah[fm], &bh[p][2]);
                }
            }
        }
    }
    __syncthreads();

    float (*KV)[68] = (float(*)[68])(smem + S_KV);
    float (*QS)[68] = (float(*)[68])(smem + S_QS);

    #pragma unroll
    for (int fm = 0; fm < 3; fm++) {
        #pragma unroll
        for (int fn = 0; fn < 4; fn++) {
            float* d = acc[fm][fn];
            int n = warp_n*32 + fn*8 + (lane & 3)*2;
            #pragma unroll
            for (int rh = 0; rh < 2; rh++) {
                int m = warp_m*48 + fm*16 + (lane >> 2) + rh*8;
                float pb = g_pbias[b*MKQV + m];
                float v0 = d[rh*2+0] + pb, v1 = d[rh*2+1] + pb;
                if (m < 64 || m >= 128) {
                    v0 = (v0 > 0.f) ? (v0 + 1.f) : expf(v0);
                    v1 = (v1 > 0.f) ? (v1 + 1.f) : expf(v1);
                }
                float2 o = make_float2(v0, v1);
                if (m < 128) *(float2*)&KV[m][n]      = o;
                else         *(float2*)&QS[m-128][n]  = o;
            }
        }
    }
    __syncthreads();

    {   // q writeout as bf16 (coalesced: 16 bf16 = 32B per thread)
        int r2 = tid >> 2, qt = tid & 3;
        __nv_bfloat16* dst = g_qh + ((size_t)b*MDm + r2)*NN + n0 + qt*16;
        uint32_t pk[8];
        #pragma unroll
        for (int j = 0; j < 8; j++) {
            float2 v = *(const float2*)&QS[r2][qt*16 + j*2];
            __nv_bfloat162 h = __float22bfloat162_rn(v);
            pk[j] = *(uint32_t*)&h;
        }
        *(uint4*)(dst)     = *(uint4*)&pk[0];
        *(uint4*)(dst + 8) = *(uint4*)&pk[4];
    }
    {
        int h = tid >> 6, d = (tid >> 2) & 15, e0 = (tid & 3) * 4;
        float m0 = 0.f, m1 = 0.f, m2 = 0.f, m3 = 0.f;
        #pragma unroll
        for (int n = 0; n < 64; n += 4) {
            float4 a  = *(const float4*)&KV[h*16 + d][n];
            float4 b0 = *(const float4*)&KV[64 + h*16 + e0 + 0][n];
            float4 b1 = *(const float4*)&KV[64 + h*16 + e0 + 1][n];
            float4 b2 = *(const float4*)&KV[64 + h*16 + e0 + 2][n];
            float4 b3 = *(const float4*)&KV[64 + h*16 + e0 + 3][n];
            m0 = fmaf(a.x,b0.x, fmaf(a.y,b0.y, fmaf(a.z,b0.z, fmaf(a.w,b0.w, m0))));
            m1 = fmaf(a.x,b1.x, fmaf(a.y,b1.y, fmaf(a.z,b1.z, fmaf(a.w,b1.w, m1))));
            m2 = fmaf(a.x,b2.x, fmaf(a.y,b2.y, fmaf(a.z,b2.z, fmaf(a.w,b2.w, m2))));
            m3 = fmaf(a.x,b3.x, fmaf(a.y,b3.y, fmaf(a.z,b3.z, fmaf(a.w,b3.w, m3))));
        }
        *(float4*)&g_Mpart[((size_t)(b*NBLK + nb))*1024 + tid*4] = make_float4(m0,m1,m2,m3);
    }
    if (tid < 64) {
        float z = 0.f;
        #pragma unroll
        for (int n = 0; n < 64; n += 4) {
            float4 a = *(const float4*)&KV[tid][n];
            z += (a.x + a.y) + (a.z + a.w);
        }
        g_Zpart[((size_t)(b*NBLK + nb))*64 + tid] = z;
    }
}

// ---------------- K3: reduce partials -> M, Z (4-way split chains) ----------
__global__ void __launch_bounds__(256) k_red(const float* __restrict__ M0,
                                             const float* __restrict__ Z0) {
    int b = blockIdx.y, chunk = blockIdx.x;
    int t = threadIdx.x;
    int li = t & 63, grp = t >> 6;
    int idx = chunk*64 + li;
    __shared__ float red[4][64];
    __shared__ float zred[4][64];

    float acc = 0.f;
    const float* base = g_Mpart + (size_t)b*NBLK*1024 + idx;
    #pragma unroll 4
    for (int nb = grp; nb < NBLK; nb += 4) acc += base[(size_t)nb*1024];
    red[grp][li] = acc;

    float zacc = 0.f;
    if (chunk == 0) {
        const float* zb = g_Zpart + (size_t)b*NBLK*64 + li;
        #pragma unroll 4
        for (int nb = grp; nb < NBLK; nb += 4) zacc += zb[(size_t)nb*64];
        zred[grp][li] = zacc;
    }
    __syncthreads();
    if (grp == 0) {
        float s = red[0][li] + red[1][li] + red[2][li] + red[3][li];
        g_M[b*1024 + idx] = s + M0[idx];
        if (chunk == 0) {
            float z = zred[0][li] + zred[1][li] + zred[2][li] + zred[3][li];
            g_Z[b*64 + li] = z + Z0[li];
        }
    }
}

// ---------------- K4: retrieval + 1-term bf16 HMMA Wout GEMM -----------------
#define O_Q    0                          // float q[64][68]      17408 (reused as ybuf)
#define O_MS   17408                      // float Ms[4][16][16]   4096
#define O_ZS   21504                      // float Zs[64]           256
#define O_RD   21760                      // float rd[4][64]       1024
#define O_YH   22784                      // bf16 y hi [64][72]    9216
#define O_AWH  32000                      // bf16 Wout hi [256][72] 36864
#define O_TOTAL 68864

__global__ void __launch_bounds__(256) k_out(const float* __restrict__ x,
                                             const float* __restrict__ bout,
                                             float* __restrict__ out) {
    extern __shared__ char smem[];
    uint32_t sb = smem_u32(smem);
    int b  = blockIdx.y;
    int n0 = blockIdx.x * 64;
    int t  = threadIdx.x;
    int lane = t & 31, wid = t >> 5;
    int warp_m = wid >> 1, warp_n = wid & 1;

    float (*q)[68]  = (float(*)[68])(smem + O_Q);
    float* Ms       = (float*)(smem + O_MS);
    float* Zs       = (float*)(smem + O_ZS);
    float (*rd)[64] = (float(*)[64])(smem + O_RD);
    __nv_bfloat16* YH  = (__nv_bfloat16*)(smem + O_YH);

    #pragma unroll
    for (int i = 0; i < 8; i++) {
        int l = t + i*256;
        int m = l >> 3, j = l & 7;
        *(uint4*)(smem + O_AWH + m*144 + j*16) = *(const uint4*)(g_WOh + m*MDm + j*8);
    }
    #pragma unroll
    for (int i = 0; i < 4; i++) {
        int idx = t + i*256;
        Ms[idx] = g_M[b*1024 + idx];
    }
    if (t < 64) Zs[t] = g_Z[b*64 + t];
    #pragma unroll
    for (int i = 0; i < 4; i++) {       // q load: bf16 -> fp32 smem
        int l = t + i*256;
        int m = l >> 4, n4 = l & 15;
        uint2 raw = *(const uint2*)(g_qh + ((size_t)b*MDm + m)*NN + n0 + n4*4);
        __nv_bfloat162 p0 = *(__nv_bfloat162*)&raw.x;
        __nv_bfloat162 p1 = *(__nv_bfloat162*)&raw.y;
        float2 f0 = __bfloat1622float2(p0);
        float2 f1 = __bfloat1622float2(p1);
        q[m][n4*4+0] = f0.x; q[m][n4*4+1] = f0.y;
        q[m][n4*4+2] = f1.x; q[m][n4*4+3] = f1.y;
    }
    __syncthreads();
    {
        int h = t >> 6, n = t & 63;
        float s = 0.f;
        #pragma unroll
        for (int d2 = 0; d2 < 16; d2++)
            s = fmaf(Zs[h*16 + d2], q[h*16 + d2][n], s);
        rd[h][n] = 1.0f / fmaxf(s, 1e-4f);
    }
    __syncthreads();
    {   // y = (M @ phi_q)/den -> bf16 in smem
        int n = t & 63, h = t >> 6;
        float qd[16];
        #pragma unroll
        for (int d2 = 0; d2 < 16; d2++) qd[d2] = q[h*16 + d2][n];
        float acc2[16];
        #pragma unroll
        for (int j = 0; j < 16; j++) acc2[j] = 0.f;
        #pragma unroll
        for (int d2 = 0; d2 < 16; d2++) {
            float qv = qd[d2];
            #pragma unroll
            for (int j = 0; j < 16; j++)
                acc2[j] = fmaf(Ms[(h*16 + d2)*16 + j], qv, acc2[j]);
        }
        float r = rd[h][n];
        #pragma unroll
        for (int j = 0; j < 16; j++)
            YH[(h*16 + j)*72 + n] = __float2bfloat16_rn(acc2[j] * r);
    }
    __syncthreads();

    // HMMA: out[256 x 64] = WoutH @ yH
    float acc[4][4][4];
    #pragma unroll
    for (int i = 0; i < 4; i++)
        #pragma unroll
        for (int j = 0; j < 4; j++)
            #pragma unroll
            for (int r = 0; r < 4; r++) acc[i][j][r] = 0.f;

    uint32_t aRowOff = (uint32_t)(warp_m*64 + (lane & 15)) * 144 + (lane >> 4) * 16;
    uint32_t bRowOff = (uint32_t)(lane & 15) * 144
                     + (uint32_t)(warp_n*32 + (lane >> 4) * 8) * 2;

    #pragma unroll
    for (int ks = 0; ks < 4; ks++) {
        uint32_t kByte = (uint32_t)(ks * 16) * 2;
        uint32_t ah[4][4], bh[2][4];
        #pragma unroll
        for (int fm = 0; fm < 4; fm++)
            ldsm4(ah[fm], sb + O_AWH + aRowOff + (uint32_t)fm*16*144 + kByte);
        #pragma unroll
        for (int p = 0; p < 2; p++)
            ldsm4t(bh[p], sb + O_YH + bRowOff + (uint32_t)(ks*16)*144 + (uint32_t)p*16*2);
        #pragma unroll
        for (int fm = 0; fm < 4; fm++) {
            #pragma unroll
            for (int p = 0; p < 2; p++) {
                mma16816(acc[fm][p*2+0], ah[fm], &bh[p][0]);
                mma16816(acc[fm][p*2+1], ah[fm], &bh[p][2]);
            }
        }
    }

    // coalesced epilogue: 4 phases of 64 rows, fragments -> smem -> float4 IO
    float gv = g_gate[b];
    float (*yb)[68] = (float(*)[68])(smem + O_Q);
    #pragma unroll
    for (int g = 0; g < 4; g++) {
        __syncthreads();
        if (warp_m == g) {
            #pragma unroll
            for (int fm = 0; fm < 4; fm++) {
                #pragma unroll
                for (int rh = 0; rh < 2; rh++) {
                    int mr = fm*16 + (lane >> 2) + rh*8;
                    float bo = bout[g*64 + mr];
                    #pragma unroll
                    for (int fn = 0; fn < 4; fn++) {
                        int n = warp_n*32 + fn*8 + (lane & 3)*2;
                        yb[mr][n]   = gv * (acc[fm][fn][rh*2+0] + bo);
                        yb[mr][n+1] = gv * (acc[fm][fn][rh*2+1] + bo);
                    }
                }
            }
        }
        __syncthreads();
        #pragma unroll
        for (int i = 0; i < 4; i++) {
            int l = t + i*256;
            int mr = l >> 4, n4 = l & 15;
            int m = g*64 + mr;
            const float* xp = x   + ((size_t)b*Cc + m)*NN + n0 + n4*4;
            float*       op = out + ((size_t)b*Cc + m)*NN + n0 + n4*4;
            float4 xv = *(const float4*)xp;
            float4 yv = *(const float4*)&yb[mr][n4*4];
            float4 r;
            r.x = xv.x + yv.x;
            r.y = xv.y + yv.y;
            r.z = xv.z + yv.z;
            r.w = xv.w + yv.w;
            *(float4*)op = r;
        }
    }
}

// ---------------- launch ----------------
extern "C" void kernel_launch(void* const* d_in, const int* in_sizes, int n_in,
                              void* d_out, int out_size) {
    const float* x      = (const float*)d_in[0];
    const float* norm_w = (const float*)d_in[1];
    const float* norm_b = (const float*)d_in[2];
    const float* Wk     = (const float*)d_in[3];
    const float* Wv     = (const float*)d_in[4];
    const float* Wq     = (const float*)d_in[5];
    const float* Wout   = (const float*)d_in[6];
    const float* bout   = (const float*)d_in[7];
    const float* M0     = (const float*)d_in[8];
    const float* Z0     = (const float*)d_in[9];
    const float* Wg1    = (const float*)d_in[10];
    const float* bg1    = (const float*)d_in[11];
    const float* Wg2    = (const float*)d_in[12];
    const float* bg2    = (const float*)d_in[13];
    float* out = (float*)d_out;

    long long mainsz = (long long)Bb * Cc * NN;
    int has_tail = ((long long)out_size >= mainsz + Bb) ? 1 : 0;

    cudaFuncSetAttribute(k_proj, cudaFuncAttributeMaxDynamicSharedMemorySize, S_TOTAL);
    cudaFuncSetAttribute(k_out,  cudaFuncAttributeMaxDynamicSharedMemorySize, O_TOTAL);

    k_stats<<<Bb*Cc, 256>>>(x);
    k_prep <<<Bb, 256>>>(norm_w, norm_b, Wk, Wv, Wq, Wout, Wg1, bg1, Wg2, bg2,
                         out, has_tail, mainsz);
    k_proj <<<dim3(NBLK, Bb), 256, S_TOTAL>>>();
    k_red  <<<dim3(16, Bb), 256>>>(M0, Z0);
    k_out  <<<dim3(NBLK, Bb), 256, O_TOTAL>>>(x, bout, out);
}

// round 15
// speedup vs baseline: 1.1557x; 1.0649x over previous
#include <cuda_runtime.h>
#include <cuda_bf16.h>
#include <math.h>
#include <stdint.h>

#define Bb   16
#define Cc   256
#define NN   9216      // H*W
#define GG   8
#define MDm  64
#define NHh  4
#define HDd  16
#define MKQV 192
#define NBLK 144       // NN/64 column blocks

// ---------------- scratch (device globals: no allocs allowed) ----------------
__device__ float g_chansum[Bb*Cc];
__device__ float g_chansq [Bb*Cc];
__device__ __nv_bfloat16 g_xh[(size_t)Bb*Cc*NN];   // x in bf16
__device__ __nv_bfloat16 g_Wh[(size_t)Bb*MKQV*Cc];
__device__ __nv_bfloat16 g_WOh[Cc*MDm];
__device__ float g_pbias  [Bb*MKQV];
__device__ float g_gate   [Bb];
__device__ __nv_bfloat16 g_qh[(size_t)Bb*MDm*NN]; // phi_q in bf16
__device__ float g_Mpart  [(size_t)Bb*NBLK*1024];
__device__ float g_Zpart  [(size_t)Bb*NBLK*64];
__device__ float g_M      [Bb*NHh*HDd*HDd];
__device__ float g_Z      [Bb*NHh*HDd];

// ---------------- PTX helpers (baseline ISA: ldmatrix/mma.sync/cp.async) -----
__device__ __forceinline__ uint32_t smem_u32(const void* p) {
    uint32_t a;
    asm("{ .reg .u64 t; cvta.to.shared.u64 t, %1; cvt.u32.u64 %0, t; }" : "=r"(a) : "l"(p));
    return a;
}
__device__ __forceinline__ void ldsm4(uint32_t* r, uint32_t addr) {
    asm volatile("ldmatrix.sync.aligned.m8n8.x4.shared.b16 {%0,%1,%2,%3}, [%4];"
        : "=r"(r[0]), "=r"(r[1]), "=r"(r[2]), "=r"(r[3]) : "r"(addr));
}
__device__ __forceinline__ void ldsm4t(uint32_t* r, uint32_t addr) {
    asm volatile("ldmatrix.sync.aligned.m8n8.x4.trans.shared.b16 {%0,%1,%2,%3}, [%4];"
        : "=r"(r[0]), "=r"(r[1]), "=r"(r[2]), "=r"(r[3]) : "r"(addr));
}
__device__ __forceinline__ void mma16816(float* d, const uint32_t* a, const uint32_t* b) {
    asm volatile("mma.sync.aligned.m16n8k16.row.col.f32.bf16.bf16.f32 "
        "{%0,%1,%2,%3}, {%4,%5,%6,%7}, {%8,%9}, {%0,%1,%2,%3};"
        : "+f"(d[0]), "+f"(d[1]), "+f"(d[2]), "+f"(d[3])
        : "r"(a[0]), "r"(a[1]), "r"(a[2]), "r"(a[3]), "r"(b[0]), "r"(b[1]));
}
__device__ __forceinline__ void cp16(uint32_t dst, const void* src) {
    asm volatile("cp.async.cg.shared.global [%0], [%1], 16;" :: "r"(dst), "l"(src));
}
#define CP_COMMIT() asm volatile("cp.async.commit_group;" ::: "memory")
#define CP_WAIT0()  asm volatile("cp.async.wait_group 0;" ::: "memory")

// ---------------- K0: per-(b,c) sum/sumsq + bf16 cast of x -------------------
__global__ void __launch_bounds__(256) k_stats(const float* __restrict__ x) {
    int bc = blockIdx.x;
    int t  = threadIdx.x;
    const float4* p = (const float4*)(x + (size_t)bc * NN);
    __nv_bfloat16* xh = g_xh + (size_t)bc * NN;
    float s = 0.f, sq = 0.f;
    #pragma unroll
    for (int i = 0; i < NN/1024; i++) {
        float4 v = p[t + i*256];
        s += (v.x + v.y) + (v.z + v.w);
        sq = fmaf(v.x, v.x, sq);
        sq = fmaf(v.y, v.y, sq);
        sq = fmaf(v.z, v.z, sq);
        sq = fmaf(v.w, v.w, sq);
        __nv_bfloat162 h01 = __float22bfloat162_rn(make_float2(v.x, v.y));
        __nv_bfloat162 h23 = __float22bfloat162_rn(make_float2(v.z, v.w));
        int e = (t + i*256) * 4;
        uint2 uh;
        uh.x = *(uint32_t*)&h01; uh.y = *(uint32_t*)&h23;
        *(uint2*)&xh[e] = uh;
    }
    #pragma unroll
    for (int o = 16; o; o >>= 1) {
        s  += __shfl_down_sync(0xffffffffu, s,  o);
        sq += __shfl_down_sync(0xffffffffu, sq, o);
    }
    __shared__ float ss[8], sqs[8];
    if ((t & 31) == 0) { ss[t>>5] = s; sqs[t>>5] = sq; }
    __syncthreads();
    if (t == 0) {
        float a = 0.f, b2 = 0.f;
        #pragma unroll
        for (int w = 0; w < 8; w++) { a += ss[w]; b2 += sqs[w]; }
        g_chansum[bc] = a;
        g_chansq [bc] = b2;
    }
}

// ---------------- K1: group stats, weight fold+bf16, Wout bf16, gate MLP -----
__global__ void __launch_bounds__(256) k_prep(
    const float* __restrict__ norm_w, const float* __restrict__ norm_b,
    const float* __restrict__ Wk, const float* __restrict__ Wv, const float* __restrict__ Wq,
    const float* __restrict__ Wout,
    const float* __restrict__ Wg1, const float* __restrict__ bg1,
    const float* __restrict__ Wg2, const float* __restrict__ bg2,
    float* __restrict__ out, int has_tail, long long tail_off)
{
    int b = blockIdx.x;
    int t = threadIdx.x;
    __shared__ float mu_s[GG], rs_s[GG];
    __shared__ float alpha_s[Cc], beta_s[Cc], pooled[Cc];
    __shared__ float g1v[MDm];

    if (b == 0) {
        #pragma unroll
        for (int j = 0; j < MDm; j++)
            g_WOh[t*MDm + j] = __float2bfloat16_rn(Wout[t*MDm + j]);
    }

    if (t < GG) {
        float s = 0.f, sq = 0.f;
        for (int c = 0; c < 32; c++) {
            s  += g_chansum[b*Cc + t*32 + c];
            sq += g_chansq [b*Cc + t*32 + c];
        }
        float inv = 1.0f / (32.0f * (float)NN);
        float mu  = s * inv;
        float var = sq * inv - mu * mu;
        mu_s[t] = mu;
        rs_s[t] = rsqrtf(var + 1e-5f);
    }
    __syncthreads();
    {
        int c = t, g = c >> 5;
        float a  = rs_s[g] * norm_w[c];
        float be = norm_b[c] - mu_s[g] * a;
        alpha_s[c] = a;
        beta_s [c] = be;
        pooled [c] = g_chansum[b*Cc + c] * (1.0f/(float)NN) * a + be;
    }
    __syncthreads();
    for (int m = 0; m < MKQV; m++) {
        const float* Wsrc = (m < 64) ? (Wk + m*Cc)
                          : (m < 128) ? (Wv + (m-64)*Cc)
                                      : (Wq + (m-128)*Cc);
        g_Wh[(size_t)b*MKQV*Cc + m*Cc + t] = __float2bfloat16_rn(Wsrc[t] * alpha_s[t]);
    }
    if (t < MKQV) {
        const float* Wsrc = (t < 64) ? (Wk + t*Cc)
                          : (t < 128) ? (Wv + (t-64)*Cc)
                                      : (Wq + (t-128)*Cc);
        float s = 0.f;
        for (int c = 0; c < Cc; c++) s = fmaf(Wsrc[c], beta_s[c], s);
        g_pbias[b*MKQV + t] = s;
    }
    __syncthreads();
    if (t < MDm) {
        float h = bg1[t];
        for (int c = 0; c < Cc; c++) h = fmaf(Wg1[t*Cc + c], pooled[c], h);
        g1v[t] = 0.5f * h * (1.0f + erff(h * 0.70710678118654752f));
    }
    __syncthreads();
    if (t == 0) {
        float s = bg2[0];
        #pragma unroll
        for (int j = 0; j < MDm; j++) s = fmaf(Wg2[j], g1v[j], s);
        float gv = 1.0f / (1.0f + expf(-s));
        g_gate[b] = gv;
        if (has_tail) out[tail_off + b] = gv;
    }
}

// ---------------- K2: 1-term bf16 HMMA KQV GEMM, cp.async dbl-buffered -------
// per-buffer: A 27648 | BH 9216 = 36864
#define P_A     0
#define P_BH    27648
#define PBUF    36864
#define S_TOTAL 73728
// epilogue union:
#define S_KV    0                         // float[128][68]  34816
#define S_QS    36864                     // float[64][68]   17408

__global__ void __launch_bounds__(256,3) k_proj() {
    extern __shared__ char smem[];
    uint32_t sb = smem_u32(smem);
    int b   = blockIdx.y;
    int nb  = blockIdx.x;
    int n0  = nb * 64;
    int tid = threadIdx.x;
    int wid = tid >> 5, lane = tid & 31;
    int warp_m = wid >> 1;
    int warp_n = wid & 1;

    const __nv_bfloat16* wh = g_Wh + (size_t)b*MKQV*Cc;
    const __nv_bfloat16* xh = g_xh + (size_t)b*Cc*NN + n0;

    float acc[3][4][4];
    #pragma unroll
    for (int i = 0; i < 3; i++)
        #pragma unroll
        for (int j = 0; j < 4; j++)
            #pragma unroll
            for (int r = 0; r < 4; r++) acc[i][j][r] = 0.f;

    uint32_t aRowOff  = (uint32_t)(warp_m*48 + (lane & 15)) * 144 + (lane >> 4) * 16;
    uint32_t bRowOff  = (uint32_t)(lane & 15) * 144
                      + (uint32_t)(warp_n*32 + (lane >> 4) * 8) * 2;

    // prologue: chunk 0 -> buffer 0
    {
        #pragma unroll
        for (int i = 0; i < 6; i++) {
            int l = tid + i*256;
            int m = l >> 3, j = l & 7;
            cp16(sb + P_A + m*144 + j*16, wh + (size_t)m*Cc + j*8);
        }
        #pragma unroll
        for (int i = 0; i < 2; i++) {
            int l = tid + i*256;
            int k = l >> 3, j = l & 7;
            cp16(sb + P_BH + k*144 + j*16, xh + (size_t)k*NN + j*8);
        }
        CP_COMMIT();
    }

    for (int c = 0; c < 4; c++) {
        uint32_t buf = (uint32_t)(c & 1) * PBUF;
        CP_WAIT0();
        __syncthreads();
        if (c < 3) {
            int kk = (c + 1) * 64;
            uint32_t nbuf = buf ^ PBUF;
            #pragma unroll
            for (int i = 0; i < 6; i++) {
                int l = tid + i*256;
                int m = l >> 3, j = l & 7;
                cp16(sb + nbuf + P_A + m*144 + j*16, wh + (size_t)m*Cc + kk + j*8);
            }
            #pragma unroll
            for (int i = 0; i < 2; i++) {
                int l = tid + i*256;
                int k = l >> 3, j = l & 7;
                cp16(sb + nbuf + P_BH + k*144 + j*16, xh + (size_t)(kk + k)*NN + j*8);
            }
            CP_COMMIT();
        }
        #pragma unroll
        for (int ks = 0; ks < 4; ks++) {
            uint32_t kByte = (uint32_t)(ks * 16) * 2;
            uint32_t ah[3][4], bh[2][4];
            #pragma unroll
            for (int fm = 0; fm < 3; fm++)
                ldsm4(ah[fm], sb + buf + P_A + aRowOff + (uint32_t)fm*16*144 + kByte);
            #pragma unroll
            for (int p = 0; p < 2; p++)
                ldsm4t(bh[p], sb + buf + P_BH + bRowOff + (uint32_t)(ks*16)*144 + (uint32_t)p*16*2);
            #pragma unroll
            for (int fm = 0; fm < 3; fm++) {
                #pragma unroll
                for (int p = 0; p < 2; p++) {
                    mma16816(acc[fm][p*2+0], ah[fm], &bh[p][0]);
                    mma16816(acc[fm][p*2+1], ah[fm], &bh[p][2]);
                }
            }
        }
    }
    __syncthreads();

    float (*KV)[68] = (float(*)[68])(smem + S_KV);
    float (*QS)[68] = (float(*)[68])(smem + S_QS);

    #pragma unroll
    for (int fm = 0; fm < 3; fm++) {
        #pragma unroll
        for (int fn = 0; fn < 4; fn++) {
            float* d = acc[fm][fn];
            int n = warp_n*32 + fn*8 + (lane & 3)*2;
            #pragma unroll
            for (int rh = 0; rh < 2; rh++) {
                int m = warp_m*48 + fm*16 + (lane >> 2) + rh*8;
                float pb = g_pbias[b*MKQV + m];
                float v0 = d[rh*2+0] + pb, v1 = d[rh*2+1] + pb;
                if (m < 64 || m >= 128) {
                    v0 = (v0 > 0.f) ? (v0 + 1.f) : expf(v0);
                    v1 = (v1 > 0.f) ? (v1 + 1.f) : expf(v1);
                }
                float2 o = make_float2(v0, v1);
                if (m < 128) *(float2*)&KV[m][n]      = o;
                else         *(float2*)&QS[m-128][n]  = o;
            }
        }
    }
    __syncthreads();

    {   // q writeout as bf16 (coalesced: 16 bf16 = 32B per thread)
        int r2 = tid >> 2, qt = tid & 3;
        __nv_bfloat16* dst = g_qh + ((size_t)b*MDm + r2)*NN + n0 + qt*16;
        uint32_t pk[8];
        #pragma unroll
        for (int j = 0; j < 8; j++) {
            float2 v = *(const float2*)&QS[r2][qt*16 + j*2];
            __nv_bfloat162 h = __float22bfloat162_rn(v);
            pk[j] = *(uint32_t*)&h;
        }
        *(uint4*)(dst)     = *(uint4*)&pk[0];
        *(uint4*)(dst + 8) = *(uint4*)&pk[4];
    }
    {
        int h = tid >> 6, d = (tid >> 2) & 15, e0 = (tid & 3) * 4;
        float m0 = 0.f, m1 = 0.f, m2 = 0.f, m3 = 0.f;
        #pragma unroll
        for (int n = 0; n < 64; n += 4) {
            float4 a  = *(const float4*)&KV[h*16 + d][n];
            float4 b0 = *(const float4*)&KV[64 + h*16 + e0 + 0][n];
            float4 b1 = *(const float4*)&KV[64 + h*16 + e0 + 1][n];
            float4 b2 = *(const float4*)&KV[64 + h*16 + e0 + 2][n];
            float4 b3 = *(const float4*)&KV[64 + h*16 + e0 + 3][n];
            m0 = fmaf(a.x,b0.x, fmaf(a.y,b0.y, fmaf(a.z,b0.z, fmaf(a.w,b0.w, m0))));
            m1 = fmaf(a.x,b1.x, fmaf(a.y,b1.y, fmaf(a.z,b1.z, fmaf(a.w,b1.w, m1))));
            m2 = fmaf(a.x,b2.x, fmaf(a.y,b2.y, fmaf(a.z,b2.z, fmaf(a.w,b2.w, m2))));
            m3 = fmaf(a.x,b3.x, fmaf(a.y,b3.y, fmaf(a.z,b3.z, fmaf(a.w,b3.w, m3))));
        }
        *(float4*)&g_Mpart[((size_t)(b*NBLK + nb))*1024 + tid*4] = make_float4(m0,m1,m2,m3);
    }
    if (tid < 64) {
        float z = 0.f;
        #pragma unroll
        for (int n = 0; n < 64; n += 4) {
            float4 a = *(const float4*)&KV[tid][n];
            z += (a.x + a.y) + (a.z + a.w);
        }
        g_Zpart[((size_t)(b*NBLK + nb))*64 + tid] = z;
    }
}

// ---------------- K3: reduce partials -> M, Z (4-way split chains) ----------
__global__ void __launch_bounds__(256) k_red(const float* __restrict__ M0,
                                             const float* __restrict__ Z0) {
    int b = blockIdx.y, chunk = blockIdx.x;
    int t = threadIdx.x;
    int li = t & 63, grp = t >> 6;
    int idx = chunk*64 + li;
    __shared__ float red[4][64];
    __shared__ float zred[4][64];

    float acc = 0.f;
    const float* base = g_Mpart + (size_t)b*NBLK*1024 + idx;
    #pragma unroll 4
    for (int nb = grp; nb < NBLK; nb += 4) acc += base[(size_t)nb*1024];
    red[grp][li] = acc;

    float zacc = 0.f;
    if (chunk == 0) {
        const float* zb = g_Zpart + (size_t)b*NBLK*64 + li;
        #pragma unroll 4
        for (int nb = grp; nb < NBLK; nb += 4) zacc += zb[(size_t)nb*64];
        zred[grp][li] = zacc;
    }
    __syncthreads();
    if (grp == 0) {
        float s = red[0][li] + red[1][li] + red[2][li] + red[3][li];
        g_M[b*1024 + idx] = s + M0[idx];
        if (chunk == 0) {
            float z = zred[0][li] + zred[1][li] + zred[2][li] + zred[3][li];
            g_Z[b*64 + li] = z + Z0[li];
        }
    }
}

// ---------------- K4: retrieval + 1-term bf16 HMMA Wout GEMM (BN=32, occ3) ---
#define O_Q    0                          // float q[64][36]       9216
#define O_MS   9216                       // float Ms[4][16][16]   4096
#define O_ZS   13312                      // float Zs[64]           256
#define O_RD   13568                      // float rd[4][32]        512
#define O_YH   14080                      // bf16 y [64][72]       9216 (32 cols used)
#define O_AWH  23296                      // bf16 Wout [256][72]  36864
#define O_TOTAL 60160

__global__ void __launch_bounds__(256,3) k_out(const float* __restrict__ x,
                                               const float* __restrict__ bout,
                                               float* __restrict__ out) {
    extern __shared__ char smem[];
    uint32_t sb = smem_u32(smem);
    int b  = blockIdx.y;
    int n0 = blockIdx.x * 32;
    int t  = threadIdx.x;
    int lane = t & 31, wid = t >> 5;   // 8 warps, each M=32 x N=32

    float (*q)[36]  = (float(*)[36])(smem + O_Q);
    float* Ms       = (float*)(smem + O_MS);
    float* Zs       = (float*)(smem + O_ZS);
    float (*rd)[32] = (float(*)[32])(smem + O_RD);
    __nv_bfloat16* YH  = (__nv_bfloat16*)(smem + O_YH);

    #pragma unroll
    for (int i = 0; i < 8; i++) {
        int l = t + i*256;
        int m = l >> 3, j = l & 7;
        *(uint4*)(smem + O_AWH + m*144 + j*16) = *(const uint4*)(g_WOh + m*MDm + j*8);
    }
    #pragma unroll
    for (int i = 0; i < 4; i++) {
        int idx = t + i*256;
        Ms[idx] = g_M[b*1024 + idx];
    }
    if (t < 64) Zs[t] = g_Z[b*64 + t];
    {   // q load: 64 rows x 32 cols bf16 -> fp32 smem (8 bf16 per thread)
        int m = t >> 2, n8 = (t & 3) * 8;
        uint4 raw = *(const uint4*)(g_qh + ((size_t)b*MDm + m)*NN + n0 + n8);
        const uint32_t* w = (const uint32_t*)&raw;
        #pragma unroll
        for (int j = 0; j < 4; j++) {
            float2 f = __bfloat1622float2(*(__nv_bfloat162*)&w[j]);
            q[m][n8 + j*2]     = f.x;
            q[m][n8 + j*2 + 1] = f.y;
        }
    }
    __syncthreads();
    if (t < 128) {
        int h = t >> 5, n = t & 31;
        float s = 0.f;
        #pragma unroll
        for (int d2 = 0; d2 < 16; d2++)
            s = fmaf(Zs[h*16 + d2], q[h*16 + d2][n], s);
        rd[h][n] = 1.0f / fmaxf(s, 1e-4f);
    }
    __syncthreads();
    {   // y = (M @ phi_q)/den -> bf16 smem; 256 threads, each 8 j's
        int jh = t >> 7, h = (t >> 5) & 3, n = t & 31;
        float qd[16];
        #pragma unroll
        for (int d2 = 0; d2 < 16; d2++) qd[d2] = q[h*16 + d2][n];
        float acc2[8];
        #pragma unroll
        for (int j = 0; j < 8; j++) acc2[j] = 0.f;
        #pragma unroll
        for (int d2 = 0; d2 < 16; d2++) {
            float qv = qd[d2];
            #pragma unroll
            for (int j = 0; j < 8; j++)
                acc2[j] = fmaf(Ms[(h*16 + d2)*16 + jh*8 + j], qv, acc2[j]);
        }
        float r = rd[h][n];
        #pragma unroll
        for (int j = 0; j < 8; j++)
            YH[(h*16 + jh*8 + j)*72 + n] = __float2bfloat16_rn(acc2[j] * r);
    }
    __syncthreads();

    // HMMA: out[256 x 32] = WoutH @ yH ; warp wid owns rows wid*32..+31
    float acc[2][4][4];
    #pragma unroll
    for (int i = 0; i < 2; i++)
        #pragma unroll
        for (int j = 0; j < 4; j++)
            #pragma unroll
            for (int r = 0; r < 4; r++) acc[i][j][r] = 0.f;

    uint32_t aRowOff = (uint32_t)(wid*32 + (lane & 15)) * 144 + (lane >> 4) * 16;
    uint32_t bRowOff = (uint32_t)(lane & 15) * 144 + (uint32_t)((lane >> 4) * 8) * 2;

    #pragma unroll
    for (int ks = 0; ks < 4; ks++) {
        uint32_t kByte = (uint32_t)(ks * 16) * 2;
        uint32_t ah[2][4], bh[2][4];
        #pragma unroll
        for (int fm = 0; fm < 2; fm++)
            ldsm4(ah[fm], sb + O_AWH + aRowOff + (uint32_t)fm*16*144 + kByte);
        #pragma unroll
        for (int p = 0; p < 2; p++)
            ldsm4t(bh[p], sb + O_YH + bRowOff + (uint32_t)(ks*16)*144 + (uint32_t)p*16*2);
        #pragma unroll
        for (int fm = 0; fm < 2; fm++) {
            #pragma unroll
            for (int p = 0; p < 2; p++) {
                mma16816(acc[fm][p*2+0], ah[fm], &bh[p][0]);
                mma16816(acc[fm][p*2+1], ah[fm], &bh[p][2]);
            }
        }
    }

    // direct epilogue (32B-sector aligned float2 stores)
    float gv = g_gate[b];
    #pragma unroll
    for (int fm = 0; fm < 2; fm++) {
        #pragma unroll
        for (int rh = 0; rh < 2; rh++) {
            int m = wid*32 + fm*16 + (lane >> 2) + rh*8;
            float bo = bout[m];
            const float* xp = x   + ((size_t)b*Cc + m)*NN + n0;
            float*       op = out + ((size_t)b*Cc + m)*NN + n0;
            #pragma unroll
            for (int fn = 0; fn < 4; fn++) {
                int n = fn*8 + (lane & 3)*2;
                float2 xv = *(const float2*)(xp + n);
                float2 r;
                r.x = xv.x + gv * (acc[fm][fn][rh*2+0] + bo);
                r.y = xv.y + gv * (acc[fm][fn][rh*2+1] + bo);
                *(float2*)(op + n) = r;
            }
        }
    }
}

// ---------------- launch ----------------
extern "C" void kernel_launch(void* const* d_in, const int* in_sizes, int n_in,
                              void* d_out, int out_size) {
    const float* x      = (const float*)d_in[0];
    const float* norm_w = (const float*)d_in[1];
    const float* norm_b = (const float*)d_in[2];
    const float* Wk     = (const float*)d_in[3];
    const float* Wv     = (const float*)d_in[4];
    const float* Wq     = (const float*)d_in[5];
    const float* Wout   = (const float*)d_in[6];
    const float* bout   = (const float*)d_in[7];
    const float* M0     = (const float*)d_in[8];
    const float* Z0     = (const float*)d_in[9];
    const float* Wg1    = (const float*)d_in[10];
    const float* bg1    = (const float*)d_in[11];
    const float* Wg2    = (const float*)d_in[12];
    const float* bg2    = (const float*)d_in[13];
    float* out = (float*)d_out;

    long long mainsz = (long long)Bb * Cc * NN;
    int has_tail = ((long long)out_size >= mainsz + Bb) ? 1 : 0;

    cudaFuncSetAttribute(k_proj, cudaFuncAttributeMaxDynamicSharedMemorySize, S_TOTAL);
    cudaFuncSetAttribute(k_out,  cudaFuncAttributeMaxDynamicSharedMemorySize, O_TOTAL);

    k_stats<<<Bb*Cc, 256>>>(x);
    k_prep <<<Bb, 256>>>(norm_w, norm_b, Wk, Wv, Wq, Wout, Wg1, bg1, Wg2, bg2,
                         out, has_tail, mainsz);
    k_proj <<<dim3(NBLK, Bb), 256, S_TOTAL>>>();
    k_red  <<<dim3(16, Bb), 256>>>(M0, Z0);
    k_out  <<<dim3(NN/32, Bb), 256, O_TOTAL>>>(x, bout, out);
}

// round 16
// speedup vs baseline: 1.1558x; 1.0001x over previous
#include <cuda_runtime.h>
#include <cuda_bf16.h>
#include <math.h>
#include <stdint.h>

#define Bb   16
#define Cc   256
#define NN   9216      // H*W
#define GG   8
#define MDm  64
#define NHh  4
#define HDd  16
#define MKQV 192
#define NBLK 144       // NN/64 column blocks

// ---------------- scratch (device globals: no allocs allowed) ----------------
__device__ float g_chansum[Bb*Cc];
__device__ float g_chansq [Bb*Cc];
__device__ __nv_bfloat16 g_xh[(size_t)Bb*Cc*NN];   // x in bf16
__device__ __nv_bfloat16 g_Wh[(size_t)Bb*MKQV*Cc];
__device__ __nv_bfloat16 g_WOh[Cc*MDm];
__device__ float g_pbias  [Bb*MKQV];
__device__ float g_gate   [Bb];
__device__ __nv_bfloat16 g_qh[(size_t)Bb*MDm*NN]; // phi_q in bf16
__device__ float g_Mpart  [(size_t)Bb*NBLK*1024];
__device__ float g_Zpart  [(size_t)Bb*NBLK*64];
__device__ float g_M      [Bb*NHh*HDd*HDd];
__device__ float g_Z      [Bb*NHh*HDd];

// ---------------- PTX helpers (baseline ISA: ldmatrix/mma.sync/cp.async) -----
__device__ __forceinline__ uint32_t smem_u32(const void* p) {
    uint32_t a;
    asm("{ .reg .u64 t; cvta.to.shared.u64 t, %1; cvt.u32.u64 %0, t; }" : "=r"(a) : "l"(p));
    return a;
}
__device__ __forceinline__ void ldsm4(uint32_t* r, uint32_t addr) {
    asm volatile("ldmatrix.sync.aligned.m8n8.x4.shared.b16 {%0,%1,%2,%3}, [%4];"
        : "=r"(r[0]), "=r"(r[1]), "=r"(r[2]), "=r"(r[3]) : "r"(addr));
}
__device__ __forceinline__ void ldsm4t(uint32_t* r, uint32_t addr) {
    asm volatile("ldmatrix.sync.aligned.m8n8.x4.trans.shared.b16 {%0,%1,%2,%3}, [%4];"
        : "=r"(r[0]), "=r"(r[1]), "=r"(r[2]), "=r"(r[3]) : "r"(addr));
}
__device__ __forceinline__ void mma16816(float* d, const uint32_t* a, const uint32_t* b) {
    asm volatile("mma.sync.aligned.m16n8k16.row.col.f32.bf16.bf16.f32 "
        "{%0,%1,%2,%3}, {%4,%5,%6,%7}, {%8,%9}, {%0,%1,%2,%3};"
        : "+f"(d[0]), "+f"(d[1]), "+f"(d[2]), "+f"(d[3])
        : "r"(a[0]), "r"(a[1]), "r"(a[2]), "r"(a[3]), "r"(b[0]), "r"(b[1]));
}
__device__ __forceinline__ void cp16(uint32_t dst, const void* src) {
    asm volatile("cp.async.cg.shared.global [%0], [%1], 16;" :: "r"(dst), "l"(src));
}
#define CP_COMMIT() asm volatile("cp.async.commit_group;" ::: "memory")
#define CP_WAIT0()  asm volatile("cp.async.wait_group 0;" ::: "memory")

// ---------------- K0: per-(b,c) sum/sumsq + bf16 cast of x -------------------
__global__ void __launch_bounds__(256) k_stats(const float* __restrict__ x) {
    int bc = blockIdx.x;
    int t  = threadIdx.x;
    const float4* p = (const float4*)(x + (size_t)bc * NN);
    __nv_bfloat16* xh = g_xh + (size_t)bc * NN;
    float s = 0.f, sq = 0.f;
    #pragma unroll
    for (int i = 0; i < NN/1024; i++) {
        float4 v = p[t + i*256];
        s += (v.x + v.y) + (v.z + v.w);
        sq = fmaf(v.x, v.x, sq);
        sq = fmaf(v.y, v.y, sq);
        sq = fmaf(v.z, v.z, sq);
        sq = fmaf(v.w, v.w, sq);
        __nv_bfloat162 h01 = __float22bfloat162_rn(make_float2(v.x, v.y));
        __nv_bfloat162 h23 = __float22bfloat162_rn(make_float2(v.z, v.w));
        int e = (t + i*256) * 4;
        uint2 uh;
        uh.x = *(uint32_t*)&h01; uh.y = *(uint32_t*)&h23;
        *(uint2*)&xh[e] = uh;
    }
    #pragma unroll
    for (int o = 16; o; o >>= 1) {
        s  += __shfl_down_sync(0xffffffffu, s,  o);
        sq += __shfl_down_sync(0xffffffffu, sq, o);
    }
    __shared__ float ss[8], sqs[8];
    if ((t & 31) == 0) { ss[t>>5] = s; sqs[t>>5] = sq; }
    __syncthreads();
    if (t == 0) {
        float a = 0.f, b2 = 0.f;
        #pragma unroll
        for (int w = 0; w < 8; w++) { a += ss[w]; b2 += sqs[w]; }
        g_chansum[bc] = a;
        g_chansq [bc] = b2;
    }
}

// ---------------- K1: group stats, weight fold+bf16, Wout bf16, gate MLP -----
__global__ void __launch_bounds__(256) k_prep(
    const float* __restrict__ norm_w, const float* __restrict__ norm_b,
    const float* __restrict__ Wk, const float* __restrict__ Wv, const float* __restrict__ Wq,
    const float* __restrict__ Wout,
    const float* __restrict__ Wg1, const float* __restrict__ bg1,
    const float* __restrict__ Wg2, const float* __restrict__ bg2,
    float* __restrict__ out, int has_tail, long long tail_off)
{
    int b = blockIdx.x;
    int t = threadIdx.x;
    __shared__ float mu_s[GG], rs_s[GG];
    __shared__ float alpha_s[Cc], beta_s[Cc], pooled[Cc];
    __shared__ float g1v[MDm];

    if (b == 0) {
        #pragma unroll
        for (int j = 0; j < MDm; j++)
            g_WOh[t*MDm + j] = __float2bfloat16_rn(Wout[t*MDm + j]);
    }

    if (t < GG) {
        float s = 0.f, sq = 0.f;
        for (int c = 0; c < 32; c++) {
            s  += g_chansum[b*Cc + t*32 + c];
            sq += g_chansq [b*Cc + t*32 + c];
        }
        float inv = 1.0f / (32.0f * (float)NN);
        float mu  = s * inv;
        float var = sq * inv - mu * mu;
        mu_s[t] = mu;
        rs_s[t] = rsqrtf(var + 1e-5f);
    }
    __syncthreads();
    {
        int c = t, g = c >> 5;
        float a  = rs_s[g] * norm_w[c];
        float be = norm_b[c] - mu_s[g] * a;
        alpha_s[c] = a;
        beta_s [c] = be;
        pooled [c] = g_chansum[b*Cc + c] * (1.0f/(float)NN) * a + be;
    }
    __syncthreads();
    for (int m = 0; m < MKQV; m++) {
        const float* Wsrc = (m < 64) ? (Wk + m*Cc)
                          : (m < 128) ? (Wv + (m-64)*Cc)
                                      : (Wq + (m-128)*Cc);
        g_Wh[(size_t)b*MKQV*Cc + m*Cc + t] = __float2bfloat16_rn(Wsrc[t] * alpha_s[t]);
    }
    if (t < MKQV) {
        const float* Wsrc = (t < 64) ? (Wk + t*Cc)
                          : (t < 128) ? (Wv + (t-64)*Cc)
                                      : (Wq + (t-128)*Cc);
        float s = 0.f;
        for (int c = 0; c < Cc; c++) s = fmaf(Wsrc[c], beta_s[c], s);
        g_pbias[b*MKQV + t] = s;
    }
    __syncthreads();
    if (t < MDm) {
        float h = bg1[t];
        for (int c = 0; c < Cc; c++) h = fmaf(Wg1[t*Cc + c], pooled[c], h);
        g1v[t] = 0.5f * h * (1.0f + erff(h * 0.70710678118654752f));
    }
    __syncthreads();
    if (t == 0) {
        float s = bg2[0];
        #pragma unroll
        for (int j = 0; j < MDm; j++) s = fmaf(Wg2[j], g1v[j], s);
        float gv = 1.0f / (1.0f + expf(-s));
        g_gate[b] = gv;
        if (has_tail) out[tail_off + b] = gv;
    }
}

// ---------------- K2: 1-term bf16 HMMA KQV GEMM, cp.async dbl-buffered -------
// per-buffer: A 27648 | BH 9216 = 36864
#define P_A     0
#define P_BH    27648
#define PBUF    36864
#define S_TOTAL 73728
// epilogue union:
#define S_KV    0                         // float[128][68]  34816
#define S_QS    36864                     // float[64][68]   17408

__global__ void __launch_bounds__(256,3) k_proj() {
    extern __shared__ char smem[];
    uint32_t sb = smem_u32(smem);
    int b   = blockIdx.y;
    int nb  = blockIdx.x;
    int n0  = nb * 64;
    int tid = threadIdx.x;
    int wid = tid >> 5, lane = tid & 31;
    int warp_m = wid >> 1;
    int warp_n = wid & 1;

    const __nv_bfloat16* wh = g_Wh + (size_t)b*MKQV*Cc;
    const __nv_bfloat16* xh = g_xh + (size_t)b*Cc*NN + n0;

    float acc[3][4][4];
    #pragma unroll
    for (int i = 0; i < 3; i++)
        #pragma unroll
        for (int j = 0; j < 4; j++)
            #pragma unroll
            for (int r = 0; r < 4; r++) acc[i][j][r] = 0.f;

    uint32_t aRowOff  = (uint32_t)(warp_m*48 + (lane & 15)) * 144 + (lane >> 4) * 16;
    uint32_t bRowOff  = (uint32_t)(lane & 15) * 144
                      + (uint32_t)(warp_n*32 + (lane >> 4) * 8) * 2;

    // prologue: chunk 0 -> buffer 0
    {
        #pragma unroll
        for (int i = 0; i < 6; i++) {
            int l = tid + i*256;
            int m = l >> 3, j = l & 7;
            cp16(sb + P_A + m*144 + j*16, wh + (size_t)m*Cc + j*8);
        }
        #pragma unroll
        for (int i = 0; i < 2; i++) {
            int l = tid + i*256;
            int k = l >> 3, j = l & 7;
            cp16(sb + P_BH + k*144 + j*16, xh + (size_t)k*NN + j*8);
        }
        CP_COMMIT();
    }

    for (int c = 0; c < 4; c++) {
        uint32_t buf = (uint32_t)(c & 1) * PBUF;
        CP_WAIT0();
        __syncthreads();
        if (c < 3) {
            int kk = (c + 1) * 64;
            uint32_t nbuf = buf ^ PBUF;
            #pragma unroll
            for (int i = 0; i < 6; i++) {
                int l = tid + i*256;
                int m = l >> 3, j = l & 7;
                cp16(sb + nbuf + P_A + m*144 + j*16, wh + (size_t)m*Cc + kk + j*8);
            }
            #pragma unroll
            for (int i = 0; i < 2; i++) {
                int l = tid + i*256;
                int k = l >> 3, j = l & 7;
                cp16(sb + nbuf + P_BH + k*144 + j*16, xh + (size_t)(kk + k)*NN + j*8);
            }
            CP_COMMIT();
        }
        #pragma unroll
        for (int ks = 0; ks < 4; ks++) {
            uint32_t kByte = (uint32_t)(ks * 16) * 2;
            uint32_t ah[3][4], bh[2][4];
            #pragma unroll
            for (int fm = 0; fm < 3; fm++)
                ldsm4(ah[fm], sb + buf + P_A + aRowOff + (uint32_t)fm*16*144 + kByte);
            #pragma unroll
            for (int p = 0; p < 2; p++)
                ldsm4t(bh[p], sb + buf + P_BH + bRowOff + (uint32_t)(ks*16)*144 + (uint32_t)p*16*2);
            #pragma unroll
            for (int fm = 0; fm < 3; fm++) {
                #pragma unroll
                for (int p = 0; p < 2; p++) {
                    mma16816(acc[fm][p*2+0], ah[fm], &bh[p][0]);
                    mma16816(acc[fm][p*2+1], ah[fm], &bh[p][2]);
                }
            }
        }
    }
    __syncthreads();

    float (*KV)[68] = (float(*)[68])(smem + S_KV);
    float (*QS)[68] = (float(*)[68])(smem + S_QS);

    #pragma unroll
    for (int fm = 0; fm < 3; fm++) {
        #pragma unroll
        for (int fn = 0; fn < 4; fn++) {
            float* d = acc[fm][fn];
            int n = warp_n*32 + fn*8 + (lane & 3)*2;
            #pragma unroll
            for (int rh = 0; rh < 2; rh++) {
                int m = warp_m*48 + fm*16 + (lane >> 2) + rh*8;
                float pb = g_pbias[b*MKQV + m];
                float v0 = d[rh*2+0] + pb, v1 = d[rh*2+1] + pb;
                if (m < 64 || m >= 128) {
                    v0 = (v0 > 0.f) ? (v0 + 1.f) : expf(v0);
                    v1 = (v1 > 0.f) ? (v1 + 1.f) : expf(v1);
                }
                float2 o = make_float2(v0, v1);
                if (m < 128) *(float2*)&KV[m][n]      = o;
                else         *(float2*)&QS[m-128][n]  = o;
            }
        }
    }
    __syncthreads();

    {   // q writeout as bf16 (coalesced: 16 bf16 = 32B per thread)
        int r2 = tid >> 2, qt = tid & 3;
        __nv_bfloat16* dst = g_qh + ((size_t)b*MDm + r2)*NN + n0 + qt*16;
        uint32_t pk[8];
        #pragma unroll
        for (int j = 0; j < 8; j++) {
            float2 v = *(const float2*)&QS[r2][qt*16 + j*2];
            __nv_bfloat162 h = __float22bfloat162_rn(v);
            pk[j] = *(uint32_t*)&h;
        }
        *(uint4*)(dst)     = *(uint4*)&pk[0];
        *(uint4*)(dst + 8) = *(uint4*)&pk[4];
    }
    {
        int h = tid >> 6, d = (tid >> 2) & 15, e0 = (tid & 3) * 4;
        float m0 = 0.f, m1 = 0.f, m2 = 0.f, m3 = 0.f;
        #pragma unroll
        for (int n = 0; n < 64; n += 4) {
            float4 a  = *(const float4*)&KV[h*16 + d][n];
            float4 b0 = *(const float4*)&KV[64 + h*16 + e0 + 0][n];
            float4 b1 = *(const float4*)&KV[64 + h*16 + e0 + 1][n];
            float4 b2 = *(const float4*)&KV[64 + h*16 + e0 + 2][n];
            float4 b3 = *(const float4*)&KV[64 + h*16 + e0 + 3][n];
            m0 = fmaf(a.x,b0.x, fmaf(a.y,b0.y, fmaf(a.z,b0.z, fmaf(a.w,b0.w, m0))));
            m1 = fmaf(a.x,b1.x, fmaf(a.y,b1.y, fmaf(a.z,b1.z, fmaf(a.w,b1.w, m1))));
            m2 = fmaf(a.x,b2.x, fmaf(a.y,b2.y, fmaf(a.z,b2.z, fmaf(a.w,b2.w, m2))));
            m3 = fmaf(a.x,b3.x, fmaf(a.y,b3.y, fmaf(a.z,b3.z, fmaf(a.w,b3.w, m3))));
        }
        *(float4*)&g_Mpart[((size_t)(b*NBLK + nb))*1024 + tid*4] = make_float4(m0,m1,m2,m3);
    }
    if (tid < 64) {
        float z = 0.f;
        #pragma unroll
        for (int n = 0; n < 64; n += 4) {
            float4 a = *(const float4*)&KV[tid][n];
            z += (a.x + a.y) + (a.z + a.w);
        }
        g_Zpart[((size_t)(b*NBLK + nb))*64 + tid] = z;
    }
}

// ---------------- K3: reduce partials -> M, Z (8-way split chains) ----------
__global__ void __launch_bounds__(256) k_red(const float* __restrict__ M0,
                                             const float* __restrict__ Z0) {
    int b = blockIdx.y, chunk = blockIdx.x;       // chunk 0..31
    int t = threadIdx.x;
    int li = t & 31, grp = t >> 5;                 // 8 nb-groups
    int idx = chunk*32 + li;
    __shared__ float red[8][32];
    __shared__ float zred[8][32];

    float acc = 0.f;
    const float* base = g_Mpart + (size_t)b*NBLK*1024 + idx;
    #pragma unroll 6
    for (int nb = grp; nb < NBLK; nb += 8) acc += base[(size_t)nb*1024];
    red[grp][li] = acc;

    if (chunk < 2) {
        int z = chunk*32 + li;
        float zacc = 0.f;
        const float* zb = g_Zpart + (size_t)b*NBLK*64 + z;
        #pragma unroll 6
        for (int nb = grp; nb < NBLK; nb += 8) zacc += zb[(size_t)nb*64];
        zred[grp][li] = zacc;
    }
    __syncthreads();
    if (grp == 0) {
        float s = 0.f;
        #pragma unroll
        for (int g = 0; g < 8; g++) s += red[g][li];
        g_M[b*1024 + idx] = s + M0[idx];
        if (chunk < 2) {
            int z = chunk*32 + li;
            float zs = 0.f;
            #pragma unroll
            for (int g = 0; g < 8; g++) zs += zred[g][li];
            g_Z[b*64 + z] = zs + Z0[z];
        }
    }
}

// ---------------- K4: retrieval + 1-term bf16 HMMA Wout GEMM (BN=32 x 2 tiles)
#define O_Q    0                          // float q[64][36]       9216
#define O_MS   9216                       // float Ms[4][16][16]   4096
#define O_ZS   13312                      // float Zs[64]           256
#define O_RD   13568                      // float rd[4][32]        512
#define O_YH   14080                      // bf16 y [64][72]       9216 (32 cols used)
#define O_AWH  23296                      // bf16 Wout [256][72]  36864
#define O_TOTAL 60160

__global__ void __launch_bounds__(256,3) k_out(const float* __restrict__ x,
                                               const float* __restrict__ bout,
                                               float* __restrict__ out) {
    extern __shared__ char smem[];
    uint32_t sb = smem_u32(smem);
    int b  = blockIdx.y;
    int nb0 = blockIdx.x * 64;
    int t  = threadIdx.x;
    int lane = t & 31, wid = t >> 5;   // 8 warps, each M=32 x N=32

    float (*q)[36]  = (float(*)[36])(smem + O_Q);
    float* Ms       = (float*)(smem + O_MS);
    float* Zs       = (float*)(smem + O_ZS);
    float (*rd)[32] = (float(*)[32])(smem + O_RD);
    __nv_bfloat16* YH  = (__nv_bfloat16*)(smem + O_YH);

    #pragma unroll
    for (int i = 0; i < 8; i++) {
        int l = t + i*256;
        int m = l >> 3, j = l & 7;
        *(uint4*)(smem + O_AWH + m*144 + j*16) = *(const uint4*)(g_WOh + m*MDm + j*8);
    }
    #pragma unroll
    for (int i = 0; i < 4; i++) {
        int idx = t + i*256;
        Ms[idx] = g_M[b*1024 + idx];
    }
    if (t < 64) Zs[t] = g_Z[b*64 + t];

    uint32_t aRowOff = (uint32_t)(wid*32 + (lane & 15)) * 144 + (lane >> 4) * 16;
    uint32_t bRowOff = (uint32_t)(lane & 15) * 144 + (uint32_t)((lane >> 4) * 8) * 2;
    float gv = g_gate[b];

    #pragma unroll
    for (int tt = 0; tt < 2; tt++) {
        int n0 = nb0 + tt*32;
        if (tt) __syncthreads();          // protect q/YH reuse from prev tile reads
        {   // q load: 64 rows x 32 cols bf16 -> fp32 smem (8 bf16 per thread)
            int m = t >> 2, n8 = (t & 3) * 8;
            uint4 raw = *(const uint4*)(g_qh + ((size_t)b*MDm + m)*NN + n0 + n8);
            const uint32_t* w = (const uint32_t*)&raw;
            #pragma unroll
            for (int j = 0; j < 4; j++) {
                float2 f = __bfloat1622float2(*(__nv_bfloat162*)&w[j]);
                q[m][n8 + j*2]     = f.x;
                q[m][n8 + j*2 + 1] = f.y;
            }
        }
        __syncthreads();
        if (t < 128) {
            int h = t >> 5, n = t & 31;
            float s = 0.f;
            #pragma unroll
            for (int d2 = 0; d2 < 16; d2++)
                s = fmaf(Zs[h*16 + d2], q[h*16 + d2][n], s);
            rd[h][n] = 1.0f / fmaxf(s, 1e-4f);
        }
        __syncthreads();
        {   // y = (M @ phi_q)/den -> bf16 smem; 256 threads, each 8 j's
            int jh = t >> 7, h = (t >> 5) & 3, n = t & 31;
            float qd[16];
            #pragma unroll
            for (int d2 = 0; d2 < 16; d2++) qd[d2] = q[h*16 + d2][n];
            float acc2[8];
            #pragma unroll
            for (int j = 0; j < 8; j++) acc2[j] = 0.f;
            #pragma unroll
            for (int d2 = 0; d2 < 16; d2++) {
                float qv = qd[d2];
                #pragma unroll
                for (int j = 0; j < 8; j++)
                    acc2[j] = fmaf(Ms[(h*16 + d2)*16 + jh*8 + j], qv, acc2[j]);
            }
            float r = rd[h][n];
            #pragma unroll
            for (int j = 0; j < 8; j++)
                YH[(h*16 + jh*8 + j)*72 + n] = __float2bfloat16_rn(acc2[j] * r);
        }
        __syncthreads();

        // HMMA: out[256 x 32] = WoutH @ yH ; warp wid owns rows wid*32..+31
        float acc[2][4][4];
        #pragma unroll
        for (int i = 0; i < 2; i++)
            #pragma unroll
            for (int j = 0; j < 4; j++)
                #pragma unroll
                for (int r = 0; r < 4; r++) acc[i][j][r] = 0.f;

        #pragma unroll
        for (int ks = 0; ks < 4; ks++) {
            uint32_t kByte = (uint32_t)(ks * 16) * 2;
            uint32_t ah[2][4], bh[2][4];
            #pragma unroll
            for (int fm = 0; fm < 2; fm++)
                ldsm4(ah[fm], sb + O_AWH + aRowOff + (uint32_t)fm*16*144 + kByte);
            #pragma unroll
            for (int p = 0; p < 2; p++)
                ldsm4t(bh[p], sb + O_YH + bRowOff + (uint32_t)(ks*16)*144 + (uint32_t)p*16*2);
            #pragma unroll
            for (int fm = 0; fm < 2; fm++) {
                #pragma unroll
                for (int p = 0; p < 2; p++) {
                    mma16816(acc[fm][p*2+0], ah[fm], &bh[p][0]);
                    mma16816(acc[fm][p*2+1], ah[fm], &bh[p][2]);
                }
            }
        }

        // direct epilogue (32B-sector aligned float2 stores)
        #pragma unroll
        for (int fm = 0; fm < 2; fm++) {
            #pragma unroll
            for (int rh = 0; rh < 2; rh++) {
                int m = wid*32 + fm*16 + (lane >> 2) + rh*8;
                float bo = bout[m];
                const float* xp = x   + ((size_t)b*Cc + m)*NN + n0;
                float*       op = out + ((size_t)b*Cc + m)*NN + n0;
                #pragma unroll
                for (int fn = 0; fn < 4; fn++) {
                    int n = fn*8 + (lane & 3)*2;
                    float2 xv = *(const float2*)(xp + n);
                    float2 r;
                    r.x = xv.x + gv * (acc[fm][fn][rh*2+0] + bo);
                    r.y = xv.y + gv * (acc[fm][fn][rh*2+1] + bo);
                    *(float2*)(op + n) = r;
                }
            }
        }
    }
}

// ---------------- launch ----------------
extern "C" void kernel_launch(void* const* d_in, const int* in_sizes, int n_in,
                              void* d_out, int out_size) {
    const float* x      = (const float*)d_in[0];
    const float* norm_w = (const float*)d_in[1];
    const float* norm_b = (const float*)d_in[2];
    const float* Wk     = (const float*)d_in[3];
    const float* Wv     = (const float*)d_in[4];
    const float* Wq     = (const float*)d_in[5];
    const float* Wout   = (const float*)d_in[6];
    const float* bout   = (const float*)d_in[7];
    const float* M0     = (const float*)d_in[8];
    const float* Z0     = (const float*)d_in[9];
    const float* Wg1    = (const float*)d_in[10];
    const float* bg1    = (const float*)d_in[11];
    const float* Wg2    = (const float*)d_in[12];
    const float* bg2    = (const float*)d_in[13];
    float* out = (float*)d_out;

    long long mainsz = (long long)Bb * Cc * NN;
    int has_tail = ((long long)out_size >= mainsz + Bb) ? 1 : 0;

    cudaFuncSetAttribute(k_proj, cudaFuncAttributeMaxDynamicSharedMemorySize, S_TOTAL);
    cudaFuncSetAttribute(k_out,  cudaFuncAttributeMaxDynamicSharedMemorySize, O_TOTAL);

    k_stats<<<Bb*Cc, 256>>>(x);
    k_prep <<<Bb, 256>>>(norm_w, norm_b, Wk, Wv, Wq, Wout, Wg1, bg1, Wg2, bg2,
                         out, has_tail, mainsz);
    k_proj <<<dim3(NBLK, Bb), 256, S_TOTAL>>>();
    k_red  <<<dim3(32, Bb), 256>>>(M0, Z0);
    k_out  <<<dim3(NN/64, Bb), 256, O_TOTAL>>>(x, bout, out);
}